// round 2
// baseline (speedup 1.0000x reference)
#include <cuda_runtime.h>
#include <cuda_bf16.h>
#include <cstdint>

// Problem constants (fixed shapes per reference)
#define NN 50000
#define EE 800000
#define FF 128

// ---------------- device scratch (no runtime alloc allowed) ----------------
__device__ float g_deg[NN];
__device__ float g_dis[NN];
__device__ float g_dis2[NN];          // self-loop norm = dis^2
__device__ int   g_src[EE];
__device__ int   g_dst[EE];
__device__ float g_norm[EE];
__device__ float g_bufA[(size_t)NN * FF];
__device__ float g_bufB[(size_t)NN * FF];
__device__ float g_bufC[(size_t)NN * FF];
__device__ float g_xw2[(size_t)NN * 2];

// ---------------- preprocessing ----------------
__global__ void k_deg_init(float* deg) {
    int i = blockIdx.x * blockDim.x + threadIdx.x;
    if (i < NN) deg[i] = 1.0f;   // self-loop weight
}

// edge_index arrives as int32 (JAX x64 disabled downgrades int64 -> int32)
__global__ void k_edge_prep(const int* __restrict__ ei,
                            const float* __restrict__ ew,
                            int* __restrict__ src, int* __restrict__ dst,
                            float* __restrict__ deg) {
    int e = blockIdx.x * blockDim.x + threadIdx.x;
    if (e >= EE) return;
    int s = ei[e];
    int d = ei[EE + e];
    src[e] = s;
    dst[e] = d;
    atomicAdd(&deg[d], ew[e]);
}

__global__ void k_dis(const float* __restrict__ deg,
                      float* __restrict__ dis, float* __restrict__ dis2) {
    int i = blockIdx.x * blockDim.x + threadIdx.x;
    if (i < NN) {
        float v = rsqrtf(deg[i]);   // deg >= 1 always (self-loop)
        dis[i] = v;
        dis2[i] = v * v;
    }
}

__global__ void k_norm(const int* __restrict__ src, const int* __restrict__ dst,
                       const float* __restrict__ ew, const float* __restrict__ dis,
                       float* __restrict__ nrm) {
    int e = blockIdx.x * blockDim.x + threadIdx.x;
    if (e >= EE) return;
    nrm[e] = dis[src[e]] * ew[e] * dis[dst[e]];
}

// ---------------- 128x128 GEMM with fused epilogue ----------------
// xw = (RELU? relu(A) : A) @ W                     [M,128]
// out = bias + dis2[row] * xw                      (self-loop + bias init for scatter)
template <bool RELU>
__global__ void __launch_bounds__(256) k_gemm128(
    const float* __restrict__ A, const float* __restrict__ W,
    const float* __restrict__ bias, const float* __restrict__ dis2,
    float* __restrict__ xw, float* __restrict__ outb, int M) {
    __shared__ float As[128][36];   // padded: conflict-free f4 stores, scalar bcast reads
    __shared__ float Ws[32][128];

    int tid = threadIdx.x;
    int row0 = blockIdx.x * 128;
    int tx = tid & 15;      // 16 col-groups of 8
    int ty = tid >> 4;      // 16 row-groups of 8

    float acc[8][8];
#pragma unroll
    for (int i = 0; i < 8; i++)
#pragma unroll
        for (int j = 0; j < 8; j++) acc[i][j] = 0.0f;

    for (int k0 = 0; k0 < 128; k0 += 32) {
        // A tile: 128 rows x 32 cols = 1024 float4 (4 per thread)
#pragma unroll
        for (int t = 0; t < 4; t++) {
            int idx = tid + t * 256;
            int r = idx >> 3;        // 8 float4 per row
            int c4 = idx & 7;
            int gr = row0 + r;
            float4 v = make_float4(0.f, 0.f, 0.f, 0.f);
            if (gr < M) v = *(const float4*)(A + (size_t)gr * FF + k0 + c4 * 4);
            if (RELU) {
                v.x = fmaxf(v.x, 0.f); v.y = fmaxf(v.y, 0.f);
                v.z = fmaxf(v.z, 0.f); v.w = fmaxf(v.w, 0.f);
            }
            *(float4*)&As[r][c4 * 4] = v;
        }
        // W tile: 32 rows x 128 cols
#pragma unroll
        for (int t = 0; t < 4; t++) {
            int idx = tid + t * 256;
            int r = idx >> 5;        // 32 float4 per row
            int c4 = idx & 31;
            *(float4*)&Ws[r][c4 * 4] = *(const float4*)(W + (size_t)(k0 + r) * FF + c4 * 4);
        }
        __syncthreads();

#pragma unroll
        for (int k = 0; k < 32; k++) {
            float a[8];
#pragma unroll
            for (int i = 0; i < 8; i++) a[i] = As[ty * 8 + i][k];
            float4 w0 = *(const float4*)&Ws[k][tx * 8];
            float4 w1 = *(const float4*)&Ws[k][tx * 8 + 4];
#pragma unroll
            for (int i = 0; i < 8; i++) {
                acc[i][0] += a[i] * w0.x; acc[i][1] += a[i] * w0.y;
                acc[i][2] += a[i] * w0.z; acc[i][3] += a[i] * w0.w;
                acc[i][4] += a[i] * w1.x; acc[i][5] += a[i] * w1.y;
                acc[i][6] += a[i] * w1.z; acc[i][7] += a[i] * w1.w;
            }
        }
        __syncthreads();
    }

    float b0[8];
#pragma unroll
    for (int j = 0; j < 8; j++) b0[j] = bias[tx * 8 + j];

#pragma unroll
    for (int i = 0; i < 8; i++) {
        int gr = row0 + ty * 8 + i;
        if (gr < M) {
            float d2 = dis2[gr];
            float4 x0 = make_float4(acc[i][0], acc[i][1], acc[i][2], acc[i][3]);
            float4 x1 = make_float4(acc[i][4], acc[i][5], acc[i][6], acc[i][7]);
            *(float4*)(xw + (size_t)gr * FF + tx * 8)     = x0;
            *(float4*)(xw + (size_t)gr * FF + tx * 8 + 4) = x1;
            float4 o0 = make_float4(b0[0] + d2 * x0.x, b0[1] + d2 * x0.y,
                                    b0[2] + d2 * x0.z, b0[3] + d2 * x0.w);
            float4 o1 = make_float4(b0[4] + d2 * x1.x, b0[5] + d2 * x1.y,
                                    b0[6] + d2 * x1.z, b0[7] + d2 * x1.w);
            *(float4*)(outb + (size_t)gr * FF + tx * 8)     = o0;
            *(float4*)(outb + (size_t)gr * FF + tx * 8 + 4) = o1;
        }
    }
}

// ---------------- edge scatter: out[dst] += norm * xw[src] (128 feats) --------
// One warp per edge; red.global.add.v4.f32 => 8 vector reductions per edge.
__global__ void __launch_bounds__(256) k_scatter128(
    const int* __restrict__ src, const int* __restrict__ dst,
    const float* __restrict__ nrm, const float* __restrict__ xw,
    float* __restrict__ outb) {
    int w = (blockIdx.x * blockDim.x + threadIdx.x) >> 5;
    if (w >= EE) return;
    int lane = threadIdx.x & 31;
    int s = src[w];
    int d = dst[w];
    float nm = nrm[w];
    float4 v = *(const float4*)(xw + (size_t)s * FF + lane * 4);
    v.x *= nm; v.y *= nm; v.z *= nm; v.w *= nm;
    float* op = outb + (size_t)d * FF + lane * 4;
    asm volatile("red.global.add.v4.f32 [%0], {%1,%2,%3,%4};"
                 :: "l"(op), "f"(v.x), "f"(v.y), "f"(v.z), "f"(v.w) : "memory");
}

// ---------------- layer 8: skinny GEMM (128 -> 2) + fused init ----------------
__global__ void __launch_bounds__(256) k_gemm2(
    const float* __restrict__ A, const float* __restrict__ W8,
    const float* __restrict__ b8, const float* __restrict__ dis2,
    float* __restrict__ xw2, float* __restrict__ outb, int M) {
    __shared__ float Ws[256];               // W8 is 128x2 = 256 floats
    int tid = threadIdx.x;
    Ws[tid] = W8[tid];
    __syncthreads();

    int w = (blockIdx.x * blockDim.x + tid) >> 5;
    if (w >= M) return;
    int lane = tid & 31;

    float4 v = *(const float4*)(A + (size_t)w * FF + lane * 4);
    v.x = fmaxf(v.x, 0.f); v.y = fmaxf(v.y, 0.f);
    v.z = fmaxf(v.z, 0.f); v.w = fmaxf(v.w, 0.f);
    int k = lane * 4;
    float s0 = v.x * Ws[(k + 0) * 2] + v.y * Ws[(k + 1) * 2] +
               v.z * Ws[(k + 2) * 2] + v.w * Ws[(k + 3) * 2];
    float s1 = v.x * Ws[(k + 0) * 2 + 1] + v.y * Ws[(k + 1) * 2 + 1] +
               v.z * Ws[(k + 2) * 2 + 1] + v.w * Ws[(k + 3) * 2 + 1];
#pragma unroll
    for (int off = 16; off; off >>= 1) {
        s0 += __shfl_xor_sync(0xFFFFFFFFu, s0, off);
        s1 += __shfl_xor_sync(0xFFFFFFFFu, s1, off);
    }
    if (lane == 0) {
        float d2 = dis2[w];
        xw2[(size_t)w * 2]     = s0;
        xw2[(size_t)w * 2 + 1] = s1;
        outb[(size_t)w * 2]     = b8[0] + d2 * s0;
        outb[(size_t)w * 2 + 1] = b8[1] + d2 * s1;
    }
}

// ---------------- edge scatter for 2 output features ----------------
__global__ void __launch_bounds__(256) k_scatter2(
    const int* __restrict__ src, const int* __restrict__ dst,
    const float* __restrict__ nrm, const float* __restrict__ xw2,
    float* __restrict__ outb) {
    int e = blockIdx.x * blockDim.x + threadIdx.x;
    if (e >= EE) return;
    int s = src[e];
    int d = dst[e];
    float nm = nrm[e];
    float2 v = *(const float2*)(xw2 + (size_t)s * 2);
    float* op = outb + (size_t)d * 2;
    asm volatile("red.global.add.v2.f32 [%0], {%1,%2};"
                 :: "l"(op), "f"(nm * v.x), "f"(nm * v.y) : "memory");
}

// ---------------- launcher ----------------
extern "C" void kernel_launch(void* const* d_in, const int* in_sizes, int n_in,
                              void* d_out, int out_size) {
    const float* x    = (const float*)d_in[0];
    const int*   ei   = (const int*)d_in[1];      // int32 (JAX x64 disabled)
    const float* ea   = (const float*)d_in[2];
    const float* W1   = (const float*)d_in[3];
    const float* b1   = (const float*)d_in[4];
    const float* Wmid = (const float*)d_in[5];
    const float* bmid = (const float*)d_in[6];
    const float* W8   = (const float*)d_in[7];
    const float* b8   = (const float*)d_in[8];
    float* out = (float*)d_out;

    float *deg, *dis, *dis2, *nrm, *bufA, *bufB, *bufC, *xw2;
    int *src, *dst;
    cudaGetSymbolAddress((void**)&deg,  g_deg);
    cudaGetSymbolAddress((void**)&dis,  g_dis);
    cudaGetSymbolAddress((void**)&dis2, g_dis2);
    cudaGetSymbolAddress((void**)&nrm,  g_norm);
    cudaGetSymbolAddress((void**)&src,  g_src);
    cudaGetSymbolAddress((void**)&dst,  g_dst);
    cudaGetSymbolAddress((void**)&bufA, g_bufA);
    cudaGetSymbolAddress((void**)&bufB, g_bufB);
    cudaGetSymbolAddress((void**)&bufC, g_bufC);
    cudaGetSymbolAddress((void**)&xw2,  g_xw2);

    const int TB = 256;
    // preprocessing (same result every call — deterministic)
    k_deg_init<<<(NN + TB - 1) / TB, TB>>>(deg);
    k_edge_prep<<<(EE + TB - 1) / TB, TB>>>(ei, ea, src, dst, deg);
    k_dis<<<(NN + TB - 1) / TB, TB>>>(deg, dis, dis2);
    k_norm<<<(EE + TB - 1) / TB, TB>>>(src, dst, ea, dis, nrm);

    const int GEMM_BLOCKS  = (NN + 127) / 128;
    const int SCAT_BLOCKS  = (int)(((long long)EE * 32 + TB - 1) / TB);

    // layer 1: in = x (no relu), xw = bufA, out = bufB
    k_gemm128<false><<<GEMM_BLOCKS, TB>>>(x, W1, b1, dis2, bufA, bufB, NN);
    k_scatter128<<<SCAT_BLOCKS, TB>>>(src, dst, nrm, bufA, bufB);

    // layers 2..7: xw always bufA; in/out ping-pong between bufB and bufC
    const float* cin = bufB;
    float* f1 = bufC;
    for (int i = 0; i < 6; i++) {
        const float* W = Wmid + (size_t)i * FF * FF;
        const float* b = bmid + (size_t)i * FF;
        k_gemm128<true><<<GEMM_BLOCKS, TB>>>(cin, W, b, dis2, bufA, f1, NN);
        k_scatter128<<<SCAT_BLOCKS, TB>>>(src, dst, nrm, bufA, f1);
        float* oldin = (float*)cin;
        cin = f1;
        f1 = oldin;
    }

    // layer 8: GEMM first (D_OUT = 2), then tiny scatter straight into d_out
    k_gemm2<<<(int)(((long long)NN * 32 + TB - 1) / TB), TB>>>(cin, W8, b8, dis2, xw2, out, NN);
    k_scatter2<<<(EE + TB - 1) / TB, TB>>>(src, dst, nrm, xw2, out);
}

// round 3
// speedup vs baseline: 1.5018x; 1.5018x over previous
#include <cuda_runtime.h>
#include <cuda_bf16.h>
#include <cstdint>

#define NN 50000
#define EE 800000
#define FF 128

// ---------------- device scratch ----------------
__device__ float g_deg[NN];
__device__ float g_dis[NN];
__device__ float g_dis2[NN];
__device__ int   g_src[EE];
__device__ int   g_dst[EE];
__device__ float g_norm[EE];
__device__ int   g_cnt[NN];
__device__ int   g_cursor[NN];
__device__ int   g_rs[NN + 1];
__device__ int   g_csrc[EE];
__device__ float g_cw[EE];
__device__ float g_bufA[(size_t)NN * FF];   // xw scratch
__device__ float g_bufB[(size_t)NN * FF];
__device__ float g_bufC[(size_t)NN * FF];
__device__ float g_xw2[(size_t)NN * 2];

// ---------------- preprocessing ----------------
__global__ void k_init(float* deg, int* cnt, int* cursor) {
    int i = blockIdx.x * blockDim.x + threadIdx.x;
    if (i < NN) { deg[i] = 1.0f; cnt[i] = 0; cursor[i] = 0; }
}

__global__ void k_edge_prep(const int* __restrict__ ei,
                            const float* __restrict__ ew,
                            int* __restrict__ src, int* __restrict__ dst,
                            float* __restrict__ deg, int* __restrict__ cnt) {
    int e = blockIdx.x * blockDim.x + threadIdx.x;
    if (e >= EE) return;
    int s = ei[e];
    int d = ei[EE + e];
    src[e] = s;
    dst[e] = d;
    atomicAdd(&deg[d], ew[e]);
    atomicAdd(&cnt[d], 1);
}

__global__ void k_dis(const float* __restrict__ deg,
                      float* __restrict__ dis, float* __restrict__ dis2) {
    int i = blockIdx.x * blockDim.x + threadIdx.x;
    if (i < NN) {
        float v = rsqrtf(deg[i]);
        dis[i] = v;
        dis2[i] = v * v;
    }
}

__global__ void k_norm(const int* __restrict__ src, const int* __restrict__ dst,
                       const float* __restrict__ ew, const float* __restrict__ dis,
                       float* __restrict__ nrm) {
    int e = blockIdx.x * blockDim.x + threadIdx.x;
    if (e >= EE) return;
    nrm[e] = dis[src[e]] * ew[e] * dis[dst[e]];
}

// single-block exclusive scan over cnt -> rs (rs[NN] = total)
__global__ void k_scan(const int* __restrict__ cnt, int* __restrict__ rs) {
    __shared__ int warp_sums[32];
    __shared__ int carry;
    int tid = threadIdx.x;
    int lane = tid & 31, wid = tid >> 5;
    if (tid == 0) carry = 0;
    __syncthreads();
    for (int base = 0; base < NN; base += 1024) {
        int i = base + tid;
        int v = (i < NN) ? cnt[i] : 0;
        int x = v;
#pragma unroll
        for (int off = 1; off < 32; off <<= 1) {
            int y = __shfl_up_sync(0xFFFFFFFFu, x, off);
            if (lane >= off) x += y;
        }
        if (lane == 31) warp_sums[wid] = x;
        __syncthreads();
        if (wid == 0) {
            int s = warp_sums[lane];
#pragma unroll
            for (int off = 1; off < 32; off <<= 1) {
                int y = __shfl_up_sync(0xFFFFFFFFu, s, off);
                if (lane >= off) s += y;
            }
            warp_sums[lane] = s;
        }
        __syncthreads();
        int warp_off = (wid == 0) ? 0 : warp_sums[wid - 1];
        int excl = carry + warp_off + (x - v);
        if (i < NN) rs[i] = excl;
        __syncthreads();
        if (tid == 0) carry += warp_sums[31];
        __syncthreads();
    }
    if (threadIdx.x == 0) rs[NN] = carry;
}

__global__ void k_fill(const int* __restrict__ src, const int* __restrict__ dst,
                       const float* __restrict__ nrm, const int* __restrict__ rs,
                       int* __restrict__ cursor,
                       int* __restrict__ csrc, float* __restrict__ cw) {
    int e = blockIdx.x * blockDim.x + threadIdx.x;
    if (e >= EE) return;
    int d = dst[e];
    int p = atomicAdd(&cursor[d], 1);
    int slot = rs[d] + p;
    csrc[slot] = src[e];
    cw[slot] = nrm[e];
}

// ---------------- 128x128 GEMM: xw = (RELU? relu(A) : A) @ W ----------------
template <bool RELU>
__global__ void __launch_bounds__(256) k_gemm128(
    const float* __restrict__ A, const float* __restrict__ W,
    float* __restrict__ xw, int M) {
    __shared__ float As[128][36];
    __shared__ float Ws[32][128];

    int tid = threadIdx.x;
    int row0 = blockIdx.x * 128;
    int tx = tid & 15;
    int ty = tid >> 4;

    float acc[8][8];
#pragma unroll
    for (int i = 0; i < 8; i++)
#pragma unroll
        for (int j = 0; j < 8; j++) acc[i][j] = 0.0f;

    for (int k0 = 0; k0 < 128; k0 += 32) {
#pragma unroll
        for (int t = 0; t < 4; t++) {
            int idx = tid + t * 256;
            int r = idx >> 3;
            int c4 = idx & 7;
            int gr = row0 + r;
            float4 v = make_float4(0.f, 0.f, 0.f, 0.f);
            if (gr < M) v = *(const float4*)(A + (size_t)gr * FF + k0 + c4 * 4);
            if (RELU) {
                v.x = fmaxf(v.x, 0.f); v.y = fmaxf(v.y, 0.f);
                v.z = fmaxf(v.z, 0.f); v.w = fmaxf(v.w, 0.f);
            }
            *(float4*)&As[r][c4 * 4] = v;
        }
#pragma unroll
        for (int t = 0; t < 4; t++) {
            int idx = tid + t * 256;
            int r = idx >> 5;
            int c4 = idx & 31;
            *(float4*)&Ws[r][c4 * 4] = *(const float4*)(W + (size_t)(k0 + r) * FF + c4 * 4);
        }
        __syncthreads();

#pragma unroll
        for (int k = 0; k < 32; k += 4) {
            float4 a4[8];
#pragma unroll
            for (int i = 0; i < 8; i++) a4[i] = *(const float4*)&As[ty * 8 + i][k];
#pragma unroll
            for (int kk = 0; kk < 4; kk++) {
                float4 w0 = *(const float4*)&Ws[k + kk][tx * 8];
                float4 w1 = *(const float4*)&Ws[k + kk][tx * 8 + 4];
#pragma unroll
                for (int i = 0; i < 8; i++) {
                    float av = (&a4[i].x)[kk];
                    acc[i][0] += av * w0.x; acc[i][1] += av * w0.y;
                    acc[i][2] += av * w0.z; acc[i][3] += av * w0.w;
                    acc[i][4] += av * w1.x; acc[i][5] += av * w1.y;
                    acc[i][6] += av * w1.z; acc[i][7] += av * w1.w;
                }
            }
        }
        __syncthreads();
    }

#pragma unroll
    for (int i = 0; i < 8; i++) {
        int gr = row0 + ty * 8 + i;
        if (gr < M) {
            *(float4*)(xw + (size_t)gr * FF + tx * 8) =
                make_float4(acc[i][0], acc[i][1], acc[i][2], acc[i][3]);
            *(float4*)(xw + (size_t)gr * FF + tx * 8 + 4) =
                make_float4(acc[i][4], acc[i][5], acc[i][6], acc[i][7]);
        }
    }
}

// ---------------- CSR aggregation: out[v] = b + dis2[v]*xw[v] + sum nrm*xw[src] ----
__global__ void __launch_bounds__(256) k_agg128(
    const int* __restrict__ rs, const int* __restrict__ csrc,
    const float* __restrict__ cw, const float* __restrict__ xw,
    const float* __restrict__ bias, const float* __restrict__ dis2,
    float* __restrict__ outb) {
    int v = (blockIdx.x * blockDim.x + threadIdx.x) >> 5;
    if (v >= NN) return;
    int lane = threadIdx.x & 31;
    const float4* xwr = (const float4*)xw;

    float4 acc = xwr[(size_t)v * 32 + lane];
    float d2 = dis2[v];
    float4 b = *(const float4*)(bias + lane * 4);
    acc.x = b.x + d2 * acc.x;
    acc.y = b.y + d2 * acc.y;
    acc.z = b.z + d2 * acc.z;
    acc.w = b.w + d2 * acc.w;

    int beg = rs[v], end = rs[v + 1];
    int i = beg;
    for (; i + 1 < end; i += 2) {
        int s0 = csrc[i],   s1 = csrc[i + 1];
        float w0 = cw[i],   w1 = cw[i + 1];
        float4 v0 = xwr[(size_t)s0 * 32 + lane];
        float4 v1 = xwr[(size_t)s1 * 32 + lane];
        acc.x += w0 * v0.x + w1 * v1.x;
        acc.y += w0 * v0.y + w1 * v1.y;
        acc.z += w0 * v0.z + w1 * v1.z;
        acc.w += w0 * v0.w + w1 * v1.w;
    }
    if (i < end) {
        int s0 = csrc[i];
        float w0 = cw[i];
        float4 v0 = xwr[(size_t)s0 * 32 + lane];
        acc.x += w0 * v0.x; acc.y += w0 * v0.y;
        acc.z += w0 * v0.z; acc.w += w0 * v0.w;
    }
    ((float4*)outb)[(size_t)v * 32 + lane] = acc;
}

// ---------------- layer 8: skinny GEMM (128 -> 2) ----------------
__global__ void __launch_bounds__(256) k_gemm2(
    const float* __restrict__ A, const float* __restrict__ W8,
    float* __restrict__ xw2, int M) {
    __shared__ float Ws[256];
    int tid = threadIdx.x;
    Ws[tid] = W8[tid];
    __syncthreads();

    int w = (blockIdx.x * blockDim.x + tid) >> 5;
    if (w >= M) return;
    int lane = tid & 31;

    float4 v = *(const float4*)(A + (size_t)w * FF + lane * 4);
    v.x = fmaxf(v.x, 0.f); v.y = fmaxf(v.y, 0.f);
    v.z = fmaxf(v.z, 0.f); v.w = fmaxf(v.w, 0.f);
    int k = lane * 4;
    float s0 = v.x * Ws[(k + 0) * 2] + v.y * Ws[(k + 1) * 2] +
               v.z * Ws[(k + 2) * 2] + v.w * Ws[(k + 3) * 2];
    float s1 = v.x * Ws[(k + 0) * 2 + 1] + v.y * Ws[(k + 1) * 2 + 1] +
               v.z * Ws[(k + 2) * 2 + 1] + v.w * Ws[(k + 3) * 2 + 1];
#pragma unroll
    for (int off = 16; off; off >>= 1) {
        s0 += __shfl_xor_sync(0xFFFFFFFFu, s0, off);
        s1 += __shfl_xor_sync(0xFFFFFFFFu, s1, off);
    }
    if (lane == 0) {
        xw2[(size_t)w * 2]     = s0;
        xw2[(size_t)w * 2 + 1] = s1;
    }
}

// ---------------- layer-8 CSR aggregation (2 feats, thread per node) -------
__global__ void __launch_bounds__(256) k_agg2(
    const int* __restrict__ rs, const int* __restrict__ csrc,
    const float* __restrict__ cw, const float* __restrict__ xw2,
    const float* __restrict__ b8, const float* __restrict__ dis2,
    float* __restrict__ outb) {
    int v = blockIdx.x * blockDim.x + threadIdx.x;
    if (v >= NN) return;
    float2 a = *(const float2*)(xw2 + (size_t)v * 2);
    float d2 = dis2[v];
    float s0 = b8[0] + d2 * a.x;
    float s1 = b8[1] + d2 * a.y;
    int end = rs[v + 1];
    for (int i = rs[v]; i < end; i++) {
        int s = csrc[i];
        float w = cw[i];
        float2 xv = *(const float2*)(xw2 + (size_t)s * 2);
        s0 += w * xv.x;
        s1 += w * xv.y;
    }
    outb[(size_t)v * 2]     = s0;
    outb[(size_t)v * 2 + 1] = s1;
}

// ---------------- launcher ----------------
extern "C" void kernel_launch(void* const* d_in, const int* in_sizes, int n_in,
                              void* d_out, int out_size) {
    const float* x    = (const float*)d_in[0];
    const int*   ei   = (const int*)d_in[1];
    const float* ea   = (const float*)d_in[2];
    const float* W1   = (const float*)d_in[3];
    const float* b1   = (const float*)d_in[4];
    const float* Wmid = (const float*)d_in[5];
    const float* bmid = (const float*)d_in[6];
    const float* W8   = (const float*)d_in[7];
    const float* b8   = (const float*)d_in[8];
    float* out = (float*)d_out;

    float *deg, *dis, *dis2, *nrm, *bufA, *bufB, *bufC, *xw2, *cw;
    int *src, *dst, *cnt, *cursor, *rs, *csrc;
    cudaGetSymbolAddress((void**)&deg,    g_deg);
    cudaGetSymbolAddress((void**)&dis,    g_dis);
    cudaGetSymbolAddress((void**)&dis2,   g_dis2);
    cudaGetSymbolAddress((void**)&nrm,    g_norm);
    cudaGetSymbolAddress((void**)&src,    g_src);
    cudaGetSymbolAddress((void**)&dst,    g_dst);
    cudaGetSymbolAddress((void**)&cnt,    g_cnt);
    cudaGetSymbolAddress((void**)&cursor, g_cursor);
    cudaGetSymbolAddress((void**)&rs,     g_rs);
    cudaGetSymbolAddress((void**)&csrc,   g_csrc);
    cudaGetSymbolAddress((void**)&cw,     g_cw);
    cudaGetSymbolAddress((void**)&bufA,   g_bufA);
    cudaGetSymbolAddress((void**)&bufB,   g_bufB);
    cudaGetSymbolAddress((void**)&bufC,   g_bufC);
    cudaGetSymbolAddress((void**)&xw2,    g_xw2);

    const int TB = 256;
    const int NB_N = (NN + TB - 1) / TB;
    const int NB_E = (EE + TB - 1) / TB;

    // CSR + norm precompute (once per launch)
    k_init<<<NB_N, TB>>>(deg, cnt, cursor);
    k_edge_prep<<<NB_E, TB>>>(ei, ea, src, dst, deg, cnt);
    k_dis<<<NB_N, TB>>>(deg, dis, dis2);
    k_norm<<<NB_E, TB>>>(src, dst, ea, dis, nrm);
    k_scan<<<1, 1024>>>(cnt, rs);
    k_fill<<<NB_E, TB>>>(src, dst, nrm, rs, cursor, csrc, cw);

    const int GEMM_BLOCKS = (NN + 127) / 128;
    const int AGG_BLOCKS  = (int)(((long long)NN * 32 + TB - 1) / TB);

    // layer 1
    k_gemm128<false><<<GEMM_BLOCKS, TB>>>(x, W1, bufA, NN);
    k_agg128<<<AGG_BLOCKS, TB>>>(rs, csrc, cw, bufA, b1, dis2, bufB);

    // layers 2..7
    const float* cin = bufB;
    float* f1 = bufC;
    for (int i = 0; i < 6; i++) {
        const float* W = Wmid + (size_t)i * FF * FF;
        const float* b = bmid + (size_t)i * FF;
        k_gemm128<true><<<GEMM_BLOCKS, TB>>>(cin, W, bufA, NN);
        k_agg128<<<AGG_BLOCKS, TB>>>(rs, csrc, cw, bufA, b, dis2, f1);
        float* oldin = (float*)cin;
        cin = f1;
        f1 = oldin;
    }

    // layer 8
    k_gemm2<<<(int)(((long long)NN * 32 + TB - 1) / TB), TB>>>(cin, W8, xw2, NN);
    k_agg2<<<NB_N, TB>>>(rs, csrc, cw, xw2, b8, dis2, out);
}

// round 4
// speedup vs baseline: 1.6780x; 1.1173x over previous
#include <cuda_runtime.h>
#include <cuda_bf16.h>
#include <cstdint>

#define NN 50000
#define EE 800000
#define FF 128

// ---------------- device scratch ----------------
__device__ float g_deg[NN];
__device__ float g_dis[NN];
__device__ float g_dis2[NN];
__device__ int   g_src[EE];
__device__ int   g_dst[EE];
__device__ float g_norm[EE];
__device__ int   g_cnt[NN];
__device__ int   g_cursor[NN];
__device__ int   g_rs[NN + 4];
__device__ int   g_csrc[EE];
__device__ float g_cw[EE];
__device__ float g_bufA[(size_t)NN * FF];
__device__ float g_bufB[(size_t)NN * FF];
__device__ float g_bufC[(size_t)NN * FF];
__device__ float g_xw2[(size_t)NN * 2];

// ---------------- preprocessing ----------------
__global__ void k_init(float* deg, int* cnt, int* cursor) {
    int i = blockIdx.x * blockDim.x + threadIdx.x;
    if (i < NN) { deg[i] = 1.0f; cnt[i] = 0; cursor[i] = 0; }
}

__global__ void k_edge_prep(const int* __restrict__ ei,
                            const float* __restrict__ ew,
                            int* __restrict__ src, int* __restrict__ dst,
                            float* __restrict__ deg, int* __restrict__ cnt) {
    int e = blockIdx.x * blockDim.x + threadIdx.x;
    if (e >= EE) return;
    int s = ei[e];
    int d = ei[EE + e];
    src[e] = s;
    dst[e] = d;
    atomicAdd(&deg[d], ew[e]);
    atomicAdd(&cnt[d], 1);
}

__global__ void k_dis(const float* __restrict__ deg,
                      float* __restrict__ dis, float* __restrict__ dis2) {
    int i = blockIdx.x * blockDim.x + threadIdx.x;
    if (i < NN) {
        float v = rsqrtf(deg[i]);
        dis[i] = v;
        dis2[i] = v * v;
    }
}

__global__ void k_norm(const int* __restrict__ src, const int* __restrict__ dst,
                       const float* __restrict__ ew, const float* __restrict__ dis,
                       float* __restrict__ nrm) {
    int e = blockIdx.x * blockDim.x + threadIdx.x;
    if (e >= EE) return;
    nrm[e] = dis[src[e]] * ew[e] * dis[dst[e]];
}

// single-block exclusive scan over cnt -> rs, vectorized int4 (NN % 4 == 0)
__global__ void k_scan(const int4* __restrict__ cnt4, int* __restrict__ rs) {
    __shared__ int warp_sums[32];
    __shared__ int carry;
    const int N4 = NN / 4;   // 12500
    int tid = threadIdx.x;
    int lane = tid & 31, wid = tid >> 5;
    if (tid == 0) carry = 0;
    __syncthreads();
    for (int base = 0; base < N4; base += 1024) {
        int i = base + tid;
        int4 v = make_int4(0, 0, 0, 0);
        if (i < N4) v = cnt4[i];
        int tsum = v.x + v.y + v.z + v.w;
        int x = tsum;
#pragma unroll
        for (int off = 1; off < 32; off <<= 1) {
            int y = __shfl_up_sync(0xFFFFFFFFu, x, off);
            if (lane >= off) x += y;
        }
        if (lane == 31) warp_sums[wid] = x;
        __syncthreads();
        if (wid == 0) {
            int s = warp_sums[lane];
#pragma unroll
            for (int off = 1; off < 32; off <<= 1) {
                int y = __shfl_up_sync(0xFFFFFFFFu, s, off);
                if (lane >= off) s += y;
            }
            warp_sums[lane] = s;
        }
        __syncthreads();
        int warp_off = (wid == 0) ? 0 : warp_sums[wid - 1];
        int excl = carry + warp_off + (x - tsum);
        if (i < N4) {
            int4 o;
            o.x = excl;
            o.y = o.x + v.x;
            o.z = o.y + v.y;
            o.w = o.z + v.z;
            *(int4*)(rs + i * 4) = o;
        }
        __syncthreads();
        if (tid == 0) carry += warp_sums[31];
        __syncthreads();
    }
    if (threadIdx.x == 0) rs[NN] = carry;
}

__global__ void k_fill(const int* __restrict__ src, const int* __restrict__ dst,
                       const float* __restrict__ nrm, const int* __restrict__ rs,
                       int* __restrict__ cursor,
                       int* __restrict__ csrc, float* __restrict__ cw) {
    int e = blockIdx.x * blockDim.x + threadIdx.x;
    if (e >= EE) return;
    int d = dst[e];
    int p = atomicAdd(&cursor[d], 1);
    int slot = rs[d] + p;
    csrc[slot] = src[e];
    cw[slot] = nrm[e];
}

// ---------------- 128x128 GEMM via packed fma.rn.f32x2 ----------------
// xw = (RELU? relu(A) : A) @ W.  Exact fp32 semantics (FFMA2 = 2x fp32 FMA).
template <bool RELU>
__global__ void __launch_bounds__(256, 2) k_gemm128(
    const float* __restrict__ A, const float* __restrict__ W,
    float* __restrict__ xw, int M) {
    __shared__ float As[128][36];    // 144B row stride: float4-aligned
    __shared__ float Ws[32][128];

    int tid = threadIdx.x;
    int row0 = blockIdx.x * 128;
    int tx = tid & 15;     // 16 col-groups of 8
    int ty = tid >> 4;     // 16 row-groups of 8

    // acc2[i][j] holds output cols {2j, 2j+1} for row i as packed f32x2
    unsigned long long acc2[8][4];
#pragma unroll
    for (int i = 0; i < 8; i++)
#pragma unroll
        for (int j = 0; j < 4; j++) acc2[i][j] = 0ull;

    for (int k0 = 0; k0 < 128; k0 += 32) {
#pragma unroll
        for (int t = 0; t < 4; t++) {
            int idx = tid + t * 256;
            int r = idx >> 3;
            int c4 = idx & 7;
            int gr = row0 + r;
            float4 v = make_float4(0.f, 0.f, 0.f, 0.f);
            if (gr < M) v = *(const float4*)(A + (size_t)gr * FF + k0 + c4 * 4);
            if (RELU) {
                v.x = fmaxf(v.x, 0.f); v.y = fmaxf(v.y, 0.f);
                v.z = fmaxf(v.z, 0.f); v.w = fmaxf(v.w, 0.f);
            }
            *(float4*)&As[r][c4 * 4] = v;
        }
#pragma unroll
        for (int t = 0; t < 4; t++) {
            int idx = tid + t * 256;
            int r = idx >> 5;
            int c4 = idx & 31;
            *(float4*)&Ws[r][c4 * 4] = *(const float4*)(W + (size_t)(k0 + r) * FF + c4 * 4);
        }
        __syncthreads();

#pragma unroll
        for (int k = 0; k < 32; k += 4) {
            float4 a4[8];
#pragma unroll
            for (int i = 0; i < 8; i++) a4[i] = *(const float4*)&As[ty * 8 + i][k];
#pragma unroll
            for (int kk = 0; kk < 4; kk++) {
                // 8 W values = 4 packed f32x2 pairs, loaded as two 16B LDS
                ulonglong2 w01 = *(const ulonglong2*)&Ws[k + kk][tx * 8];
                ulonglong2 w23 = *(const ulonglong2*)&Ws[k + kk][tx * 8 + 4];
#pragma unroll
                for (int i = 0; i < 8; i++) {
                    unsigned int av = __float_as_uint((&a4[i].x)[kk]);
                    unsigned long long ad;
                    asm("mov.b64 %0, {%1, %1};" : "=l"(ad) : "r"(av));
                    asm("fma.rn.f32x2 %0, %1, %2, %0;" : "+l"(acc2[i][0]) : "l"(ad), "l"(w01.x));
                    asm("fma.rn.f32x2 %0, %1, %2, %0;" : "+l"(acc2[i][1]) : "l"(ad), "l"(w01.y));
                    asm("fma.rn.f32x2 %0, %1, %2, %0;" : "+l"(acc2[i][2]) : "l"(ad), "l"(w23.x));
                    asm("fma.rn.f32x2 %0, %1, %2, %0;" : "+l"(acc2[i][3]) : "l"(ad), "l"(w23.y));
                }
            }
        }
        __syncthreads();
    }

#pragma unroll
    for (int i = 0; i < 8; i++) {
        int gr = row0 + ty * 8 + i;
        if (gr < M) {
            float o[8];
#pragma unroll
            for (int j = 0; j < 4; j++) {
                unsigned int lo, hi;
                asm("mov.b64 {%0, %1}, %2;" : "=r"(lo), "=r"(hi) : "l"(acc2[i][j]));
                o[2 * j]     = __uint_as_float(lo);
                o[2 * j + 1] = __uint_as_float(hi);
            }
            *(float4*)(xw + (size_t)gr * FF + tx * 8) =
                make_float4(o[0], o[1], o[2], o[3]);
            *(float4*)(xw + (size_t)gr * FF + tx * 8 + 4) =
                make_float4(o[4], o[5], o[6], o[7]);
        }
    }
}

// ---------------- CSR aggregation: out[v] = b + dis2[v]*xw[v] + sum nrm*xw[src] ----
__global__ void __launch_bounds__(256) k_agg128(
    const int* __restrict__ rs, const int* __restrict__ csrc,
    const float* __restrict__ cw, const float* __restrict__ xw,
    const float* __restrict__ bias, const float* __restrict__ dis2,
    float* __restrict__ outb) {
    int v = (blockIdx.x * blockDim.x + threadIdx.x) >> 5;
    if (v >= NN) return;
    int lane = threadIdx.x & 31;
    const float4* xwr = (const float4*)xw;

    float4 acc = xwr[(size_t)v * 32 + lane];
    float d2 = dis2[v];
    float4 b = *(const float4*)(bias + lane * 4);
    acc.x = b.x + d2 * acc.x;
    acc.y = b.y + d2 * acc.y;
    acc.z = b.z + d2 * acc.z;
    acc.w = b.w + d2 * acc.w;

    int beg = rs[v], end = rs[v + 1];
    int i = beg;
    for (; i + 1 < end; i += 2) {
        int s0 = csrc[i],   s1 = csrc[i + 1];
        float w0 = cw[i],   w1 = cw[i + 1];
        float4 v0 = xwr[(size_t)s0 * 32 + lane];
        float4 v1 = xwr[(size_t)s1 * 32 + lane];
        acc.x += w0 * v0.x + w1 * v1.x;
        acc.y += w0 * v0.y + w1 * v1.y;
        acc.z += w0 * v0.z + w1 * v1.z;
        acc.w += w0 * v0.w + w1 * v1.w;
    }
    if (i < end) {
        int s0 = csrc[i];
        float w0 = cw[i];
        float4 v0 = xwr[(size_t)s0 * 32 + lane];
        acc.x += w0 * v0.x; acc.y += w0 * v0.y;
        acc.z += w0 * v0.z; acc.w += w0 * v0.w;
    }
    ((float4*)outb)[(size_t)v * 32 + lane] = acc;
}

// ---------------- layer 8: skinny GEMM (128 -> 2) ----------------
__global__ void __launch_bounds__(256) k_gemm2(
    const float* __restrict__ A, const float* __restrict__ W8,
    float* __restrict__ xw2, int M) {
    __shared__ float Ws[256];
    int tid = threadIdx.x;
    Ws[tid] = W8[tid];
    __syncthreads();

    int w = (blockIdx.x * blockDim.x + tid) >> 5;
    if (w >= M) return;
    int lane = tid & 31;

    float4 v = *(const float4*)(A + (size_t)w * FF + lane * 4);
    v.x = fmaxf(v.x, 0.f); v.y = fmaxf(v.y, 0.f);
    v.z = fmaxf(v.z, 0.f); v.w = fmaxf(v.w, 0.f);
    int k = lane * 4;
    float s0 = v.x * Ws[(k + 0) * 2] + v.y * Ws[(k + 1) * 2] +
               v.z * Ws[(k + 2) * 2] + v.w * Ws[(k + 3) * 2];
    float s1 = v.x * Ws[(k + 0) * 2 + 1] + v.y * Ws[(k + 1) * 2 + 1] +
               v.z * Ws[(k + 2) * 2 + 1] + v.w * Ws[(k + 3) * 2 + 1];
#pragma unroll
    for (int off = 16; off; off >>= 1) {
        s0 += __shfl_xor_sync(0xFFFFFFFFu, s0, off);
        s1 += __shfl_xor_sync(0xFFFFFFFFu, s1, off);
    }
    if (lane == 0) {
        xw2[(size_t)w * 2]     = s0;
        xw2[(size_t)w * 2 + 1] = s1;
    }
}

// ---------------- layer-8 CSR aggregation (2 feats) ----------------
__global__ void __launch_bounds__(256) k_agg2(
    const int* __restrict__ rs, const int* __restrict__ csrc,
    const float* __restrict__ cw, const float* __restrict__ xw2,
    const float* __restrict__ b8, const float* __restrict__ dis2,
    float* __restrict__ outb) {
    int v = blockIdx.x * blockDim.x + threadIdx.x;
    if (v >= NN) return;
    float2 a = *(const float2*)(xw2 + (size_t)v * 2);
    float d2 = dis2[v];
    float s0 = b8[0] + d2 * a.x;
    float s1 = b8[1] + d2 * a.y;
    int end = rs[v + 1];
    for (int i = rs[v]; i < end; i++) {
        int s = csrc[i];
        float w = cw[i];
        float2 xv = *(const float2*)(xw2 + (size_t)s * 2);
        s0 += w * xv.x;
        s1 += w * xv.y;
    }
    outb[(size_t)v * 2]     = s0;
    outb[(size_t)v * 2 + 1] = s1;
}

// ---------------- launcher ----------------
extern "C" void kernel_launch(void* const* d_in, const int* in_sizes, int n_in,
                              void* d_out, int out_size) {
    const float* x    = (const float*)d_in[0];
    const int*   ei   = (const int*)d_in[1];
    const float* ea   = (const float*)d_in[2];
    const float* W1   = (const float*)d_in[3];
    const float* b1   = (const float*)d_in[4];
    const float* Wmid = (const float*)d_in[5];
    const float* bmid = (const float*)d_in[6];
    const float* W8   = (const float*)d_in[7];
    const float* b8   = (const float*)d_in[8];
    float* out = (float*)d_out;

    float *deg, *dis, *dis2, *nrm, *bufA, *bufB, *bufC, *xw2, *cw;
    int *src, *dst, *cnt, *cursor, *rs, *csrc;
    cudaGetSymbolAddress((void**)&deg,    g_deg);
    cudaGetSymbolAddress((void**)&dis,    g_dis);
    cudaGetSymbolAddress((void**)&dis2,   g_dis2);
    cudaGetSymbolAddress((void**)&nrm,    g_norm);
    cudaGetSymbolAddress((void**)&src,    g_src);
    cudaGetSymbolAddress((void**)&dst,    g_dst);
    cudaGetSymbolAddress((void**)&cnt,    g_cnt);
    cudaGetSymbolAddress((void**)&cursor, g_cursor);
    cudaGetSymbolAddress((void**)&rs,     g_rs);
    cudaGetSymbolAddress((void**)&csrc,   g_csrc);
    cudaGetSymbolAddress((void**)&cw,     g_cw);
    cudaGetSymbolAddress((void**)&bufA,   g_bufA);
    cudaGetSymbolAddress((void**)&bufB,   g_bufB);
    cudaGetSymbolAddress((void**)&bufC,   g_bufC);
    cudaGetSymbolAddress((void**)&xw2,    g_xw2);

    const int TB = 256;
    const int NB_N = (NN + TB - 1) / TB;
    const int NB_E = (EE + TB - 1) / TB;

    // CSR + norm precompute (once per launch)
    k_init<<<NB_N, TB>>>(deg, cnt, cursor);
    k_edge_prep<<<NB_E, TB>>>(ei, ea, src, dst, deg, cnt);
    k_dis<<<NB_N, TB>>>(deg, dis, dis2);
    k_norm<<<NB_E, TB>>>(src, dst, ea, dis, nrm);
    k_scan<<<1, 1024>>>((const int4*)cnt, rs);
    k_fill<<<NB_E, TB>>>(src, dst, nrm, rs, cursor, csrc, cw);

    const int GEMM_BLOCKS = (NN + 127) / 128;
    const int AGG_BLOCKS  = (int)(((long long)NN * 32 + TB - 1) / TB);

    // layer 1
    k_gemm128<false><<<GEMM_BLOCKS, TB>>>(x, W1, bufA, NN);
    k_agg128<<<AGG_BLOCKS, TB>>>(rs, csrc, cw, bufA, b1, dis2, bufB);

    // layers 2..7
    const float* cin = bufB;
    float* f1 = bufC;
    for (int i = 0; i < 6; i++) {
        const float* W = Wmid + (size_t)i * FF * FF;
        const float* b = bmid + (size_t)i * FF;
        k_gemm128<true><<<GEMM_BLOCKS, TB>>>(cin, W, bufA, NN);
        k_agg128<<<AGG_BLOCKS, TB>>>(rs, csrc, cw, bufA, b, dis2, f1);
        float* oldin = (float*)cin;
        cin = f1;
        f1 = oldin;
    }

    // layer 8
    k_gemm2<<<(int)(((long long)NN * 32 + TB - 1) / TB), TB>>>(cin, W8, xw2, NN);
    k_agg2<<<NB_N, TB>>>(rs, csrc, cw, xw2, b8, dis2, out);
}

// round 5
// speedup vs baseline: 1.7202x; 1.0252x over previous
#include <cuda_runtime.h>
#include <cuda_bf16.h>
#include <cstdint>

#define NN 50000
#define EE 800000
#define FF 128

// ---------------- device scratch ----------------
__device__ float g_deg[NN];
__device__ float g_dis[NN];
__device__ float g_dis2[NN];
__device__ int   g_cnt[NN];
__device__ int   g_cursor[NN];
__device__ int   g_rs[NN + 4];
__device__ int   g_csrc[EE];
__device__ float g_cw[EE];
__device__ float g_bufA[(size_t)NN * FF];
__device__ float g_bufB[(size_t)NN * FF];
__device__ float g_bufC[(size_t)NN * FF];
__device__ float g_xw2[(size_t)NN * 2];

// ---------------- preprocessing ----------------
__global__ void k_init(float* deg, int* cnt, int* cursor) {
    int i = blockIdx.x * blockDim.x + threadIdx.x;
    if (i < NN) { deg[i] = 1.0f; cnt[i] = 0; cursor[i] = 0; }
}

__global__ void k_edge_prep(const int* __restrict__ ei,
                            const float* __restrict__ ew,
                            float* __restrict__ deg, int* __restrict__ cnt) {
    int e = blockIdx.x * blockDim.x + threadIdx.x;
    if (e >= EE) return;
    int d = ei[EE + e];
    atomicAdd(&deg[d], ew[e]);
    atomicAdd(&cnt[d], 1);
}

__global__ void k_dis(const float* __restrict__ deg,
                      float* __restrict__ dis, float* __restrict__ dis2) {
    int i = blockIdx.x * blockDim.x + threadIdx.x;
    if (i < NN) {
        float v = rsqrtf(deg[i]);
        dis[i] = v;
        dis2[i] = v * v;
    }
}

// single-block exclusive scan over cnt -> rs, vectorized int4 (NN % 4 == 0)
__global__ void k_scan(const int4* __restrict__ cnt4, int* __restrict__ rs) {
    __shared__ int warp_sums[32];
    __shared__ int carry;
    const int N4 = NN / 4;
    int tid = threadIdx.x;
    int lane = tid & 31, wid = tid >> 5;
    if (tid == 0) carry = 0;
    __syncthreads();
    for (int base = 0; base < N4; base += 1024) {
        int i = base + tid;
        int4 v = make_int4(0, 0, 0, 0);
        if (i < N4) v = cnt4[i];
        int tsum = v.x + v.y + v.z + v.w;
        int x = tsum;
#pragma unroll
        for (int off = 1; off < 32; off <<= 1) {
            int y = __shfl_up_sync(0xFFFFFFFFu, x, off);
            if (lane >= off) x += y;
        }
        if (lane == 31) warp_sums[wid] = x;
        __syncthreads();
        if (wid == 0) {
            int s = warp_sums[lane];
#pragma unroll
            for (int off = 1; off < 32; off <<= 1) {
                int y = __shfl_up_sync(0xFFFFFFFFu, s, off);
                if (lane >= off) s += y;
            }
            warp_sums[lane] = s;
        }
        __syncthreads();
        int warp_off = (wid == 0) ? 0 : warp_sums[wid - 1];
        int excl = carry + warp_off + (x - tsum);
        if (i < N4) {
            int4 o;
            o.x = excl;
            o.y = o.x + v.x;
            o.z = o.y + v.y;
            o.w = o.z + v.z;
            *(int4*)(rs + i * 4) = o;
        }
        __syncthreads();
        if (tid == 0) carry += warp_sums[31];
        __syncthreads();
    }
    if (threadIdx.x == 0) rs[NN] = carry;
}

// fill CSR slots with src index and fused normalization weight
__global__ void k_fill(const int* __restrict__ ei, const float* __restrict__ ew,
                       const float* __restrict__ dis, const int* __restrict__ rs,
                       int* __restrict__ cursor,
                       int* __restrict__ csrc, float* __restrict__ cw) {
    int e = blockIdx.x * blockDim.x + threadIdx.x;
    if (e >= EE) return;
    int s = ei[e];
    int d = ei[EE + e];
    float nrm = dis[s] * ew[e] * dis[d];
    int p = atomicAdd(&cursor[d], 1);
    int slot = rs[d] + p;
    csrc[slot] = s;
    cw[slot] = nrm;
}

// ---------------- 128x128 GEMM via packed fma.rn.f32x2 ----------------
template <bool RELU>
__global__ void __launch_bounds__(256, 2) k_gemm128(
    const float* __restrict__ A, const float* __restrict__ W,
    float* __restrict__ xw, int M) {
    __shared__ float As[128][36];
    __shared__ float Ws[32][128];

    int tid = threadIdx.x;
    int row0 = blockIdx.x * 128;
    int tx = tid & 15;
    int ty = tid >> 4;

    unsigned long long acc2[8][4];
#pragma unroll
    for (int i = 0; i < 8; i++)
#pragma unroll
        for (int j = 0; j < 4; j++) acc2[i][j] = 0ull;

    for (int k0 = 0; k0 < 128; k0 += 32) {
#pragma unroll
        for (int t = 0; t < 4; t++) {
            int idx = tid + t * 256;
            int r = idx >> 3;
            int c4 = idx & 7;
            int gr = row0 + r;
            float4 v = make_float4(0.f, 0.f, 0.f, 0.f);
            if (gr < M) v = *(const float4*)(A + (size_t)gr * FF + k0 + c4 * 4);
            if (RELU) {
                v.x = fmaxf(v.x, 0.f); v.y = fmaxf(v.y, 0.f);
                v.z = fmaxf(v.z, 0.f); v.w = fmaxf(v.w, 0.f);
            }
            *(float4*)&As[r][c4 * 4] = v;
        }
#pragma unroll
        for (int t = 0; t < 4; t++) {
            int idx = tid + t * 256;
            int r = idx >> 5;
            int c4 = idx & 31;
            *(float4*)&Ws[r][c4 * 4] = *(const float4*)(W + (size_t)(k0 + r) * FF + c4 * 4);
        }
        __syncthreads();

#pragma unroll
        for (int k = 0; k < 32; k += 4) {
            float4 a4[8];
#pragma unroll
            for (int i = 0; i < 8; i++) a4[i] = *(const float4*)&As[ty * 8 + i][k];
#pragma unroll
            for (int kk = 0; kk < 4; kk++) {
                ulonglong2 w01 = *(const ulonglong2*)&Ws[k + kk][tx * 8];
                ulonglong2 w23 = *(const ulonglong2*)&Ws[k + kk][tx * 8 + 4];
#pragma unroll
                for (int i = 0; i < 8; i++) {
                    unsigned int av = __float_as_uint((&a4[i].x)[kk]);
                    unsigned long long ad;
                    asm("mov.b64 %0, {%1, %1};" : "=l"(ad) : "r"(av));
                    asm("fma.rn.f32x2 %0, %1, %2, %0;" : "+l"(acc2[i][0]) : "l"(ad), "l"(w01.x));
                    asm("fma.rn.f32x2 %0, %1, %2, %0;" : "+l"(acc2[i][1]) : "l"(ad), "l"(w01.y));
                    asm("fma.rn.f32x2 %0, %1, %2, %0;" : "+l"(acc2[i][2]) : "l"(ad), "l"(w23.x));
                    asm("fma.rn.f32x2 %0, %1, %2, %0;" : "+l"(acc2[i][3]) : "l"(ad), "l"(w23.y));
                }
            }
        }
        __syncthreads();
    }

#pragma unroll
    for (int i = 0; i < 8; i++) {
        int gr = row0 + ty * 8 + i;
        if (gr < M) {
            float o[8];
#pragma unroll
            for (int j = 0; j < 4; j++) {
                unsigned int lo, hi;
                asm("mov.b64 {%0, %1}, %2;" : "=r"(lo), "=r"(hi) : "l"(acc2[i][j]));
                o[2 * j]     = __uint_as_float(lo);
                o[2 * j + 1] = __uint_as_float(hi);
            }
            *(float4*)(xw + (size_t)gr * FF + tx * 8) =
                make_float4(o[0], o[1], o[2], o[3]);
            *(float4*)(xw + (size_t)gr * FF + tx * 8 + 4) =
                make_float4(o[4], o[5], o[6], o[7]);
        }
    }
}

// ---------------- CSR aggregation (unroll x4, batched loads for MLP) ------
__global__ void __launch_bounds__(256) k_agg128(
    const int* __restrict__ rs, const int* __restrict__ csrc,
    const float* __restrict__ cw, const float* __restrict__ xw,
    const float* __restrict__ bias, const float* __restrict__ dis2,
    float* __restrict__ outb) {
    int v = (blockIdx.x * blockDim.x + threadIdx.x) >> 5;
    if (v >= NN) return;
    int lane = threadIdx.x & 31;
    const float4* xwr = (const float4*)xw;

    float4 acc = xwr[(size_t)v * 32 + lane];
    float d2 = dis2[v];
    float4 b = *(const float4*)(bias + lane * 4);
    acc.x = b.x + d2 * acc.x;
    acc.y = b.y + d2 * acc.y;
    acc.z = b.z + d2 * acc.z;
    acc.w = b.w + d2 * acc.w;

    int beg = rs[v], end = rs[v + 1];
    int i = beg;
    // unroll 4: batch all index/weight/gather loads up front (MLP ~12)
    for (; i + 3 < end; i += 4) {
        int s0 = csrc[i],     s1 = csrc[i + 1];
        int s2 = csrc[i + 2], s3 = csrc[i + 3];
        float w0 = cw[i],     w1 = cw[i + 1];
        float w2 = cw[i + 2], w3 = cw[i + 3];
        float4 v0 = xwr[(size_t)s0 * 32 + lane];
        float4 v1 = xwr[(size_t)s1 * 32 + lane];
        float4 v2 = xwr[(size_t)s2 * 32 + lane];
        float4 v3 = xwr[(size_t)s3 * 32 + lane];
        acc.x += w0 * v0.x; acc.y += w0 * v0.y; acc.z += w0 * v0.z; acc.w += w0 * v0.w;
        acc.x += w1 * v1.x; acc.y += w1 * v1.y; acc.z += w1 * v1.z; acc.w += w1 * v1.w;
        acc.x += w2 * v2.x; acc.y += w2 * v2.y; acc.z += w2 * v2.z; acc.w += w2 * v2.w;
        acc.x += w3 * v3.x; acc.y += w3 * v3.y; acc.z += w3 * v3.z; acc.w += w3 * v3.w;
    }
    for (; i < end; i++) {
        int s0 = csrc[i];
        float w0 = cw[i];
        float4 v0 = xwr[(size_t)s0 * 32 + lane];
        acc.x += w0 * v0.x; acc.y += w0 * v0.y;
        acc.z += w0 * v0.z; acc.w += w0 * v0.w;
    }
    ((float4*)outb)[(size_t)v * 32 + lane] = acc;
}

// ---------------- layer 8: skinny GEMM (128 -> 2) ----------------
__global__ void __launch_bounds__(256) k_gemm2(
    const float* __restrict__ A, const float* __restrict__ W8,
    float* __restrict__ xw2, int M) {
    __shared__ float Ws[256];
    int tid = threadIdx.x;
    Ws[tid] = W8[tid];
    __syncthreads();

    int w = (blockIdx.x * blockDim.x + tid) >> 5;
    if (w >= M) return;
    int lane = tid & 31;

    float4 v = *(const float4*)(A + (size_t)w * FF + lane * 4);
    v.x = fmaxf(v.x, 0.f); v.y = fmaxf(v.y, 0.f);
    v.z = fmaxf(v.z, 0.f); v.w = fmaxf(v.w, 0.f);
    int k = lane * 4;
    float s0 = v.x * Ws[(k + 0) * 2] + v.y * Ws[(k + 1) * 2] +
               v.z * Ws[(k + 2) * 2] + v.w * Ws[(k + 3) * 2];
    float s1 = v.x * Ws[(k + 0) * 2 + 1] + v.y * Ws[(k + 1) * 2 + 1] +
               v.z * Ws[(k + 2) * 2 + 1] + v.w * Ws[(k + 3) * 2 + 1];
#pragma unroll
    for (int off = 16; off; off >>= 1) {
        s0 += __shfl_xor_sync(0xFFFFFFFFu, s0, off);
        s1 += __shfl_xor_sync(0xFFFFFFFFu, s1, off);
    }
    if (lane == 0) {
        xw2[(size_t)w * 2]     = s0;
        xw2[(size_t)w * 2 + 1] = s1;
    }
}

// ---------------- layer-8 CSR aggregation (2 feats) ----------------
__global__ void __launch_bounds__(256) k_agg2(
    const int* __restrict__ rs, const int* __restrict__ csrc,
    const float* __restrict__ cw, const float* __restrict__ xw2,
    const float* __restrict__ b8, const float* __restrict__ dis2,
    float* __restrict__ outb) {
    int v = blockIdx.x * blockDim.x + threadIdx.x;
    if (v >= NN) return;
    float2 a = *(const float2*)(xw2 + (size_t)v * 2);
    float d2 = dis2[v];
    float s0 = b8[0] + d2 * a.x;
    float s1 = b8[1] + d2 * a.y;
    int end = rs[v + 1];
    for (int i = rs[v]; i < end; i++) {
        int s = csrc[i];
        float w = cw[i];
        float2 xv = *(const float2*)(xw2 + (size_t)s * 2);
        s0 += w * xv.x;
        s1 += w * xv.y;
    }
    outb[(size_t)v * 2]     = s0;
    outb[(size_t)v * 2 + 1] = s1;
}

// ---------------- launcher ----------------
extern "C" void kernel_launch(void* const* d_in, const int* in_sizes, int n_in,
                              void* d_out, int out_size) {
    const float* x    = (const float*)d_in[0];
    const int*   ei   = (const int*)d_in[1];
    const float* ea   = (const float*)d_in[2];
    const float* W1   = (const float*)d_in[3];
    const float* b1   = (const float*)d_in[4];
    const float* Wmid = (const float*)d_in[5];
    const float* bmid = (const float*)d_in[6];
    const float* W8   = (const float*)d_in[7];
    const float* b8   = (const float*)d_in[8];
    float* out = (float*)d_out;

    float *deg, *dis, *dis2, *bufA, *bufB, *bufC, *xw2, *cw;
    int *cnt, *cursor, *rs, *csrc;
    cudaGetSymbolAddress((void**)&deg,    g_deg);
    cudaGetSymbolAddress((void**)&dis,    g_dis);
    cudaGetSymbolAddress((void**)&dis2,   g_dis2);
    cudaGetSymbolAddress((void**)&cnt,    g_cnt);
    cudaGetSymbolAddress((void**)&cursor, g_cursor);
    cudaGetSymbolAddress((void**)&rs,     g_rs);
    cudaGetSymbolAddress((void**)&csrc,   g_csrc);
    cudaGetSymbolAddress((void**)&cw,     g_cw);
    cudaGetSymbolAddress((void**)&bufA,   g_bufA);
    cudaGetSymbolAddress((void**)&bufB,   g_bufB);
    cudaGetSymbolAddress((void**)&bufC,   g_bufC);
    cudaGetSymbolAddress((void**)&xw2,    g_xw2);

    const int TB = 256;
    const int NB_N = (NN + TB - 1) / TB;
    const int NB_E = (EE + TB - 1) / TB;

    // CSR + norm precompute (once per launch)
    k_init<<<NB_N, TB>>>(deg, cnt, cursor);
    k_edge_prep<<<NB_E, TB>>>(ei, ea, deg, cnt);
    k_dis<<<NB_N, TB>>>(deg, dis, dis2);
    k_scan<<<1, 1024>>>((const int4*)cnt, rs);
    k_fill<<<NB_E, TB>>>(ei, ea, dis, rs, cursor, csrc, cw);

    const int GEMM_BLOCKS = (NN + 127) / 128;
    const int AGG_BLOCKS  = (int)(((long long)NN * 32 + TB - 1) / TB);

    // layer 1
    k_gemm128<false><<<GEMM_BLOCKS, TB>>>(x, W1, bufA, NN);
    k_agg128<<<AGG_BLOCKS, TB>>>(rs, csrc, cw, bufA, b1, dis2, bufB);

    // layers 2..7
    const float* cin = bufB;
    float* f1 = bufC;
    for (int i = 0; i < 6; i++) {
        const float* W = Wmid + (size_t)i * FF * FF;
        const float* b = bmid + (size_t)i * FF;
        k_gemm128<true><<<GEMM_BLOCKS, TB>>>(cin, W, bufA, NN);
        k_agg128<<<AGG_BLOCKS, TB>>>(rs, csrc, cw, bufA, b, dis2, f1);
        float* oldin = (float*)cin;
        cin = f1;
        f1 = oldin;
    }

    // layer 8
    k_gemm2<<<(int)(((long long)NN * 32 + TB - 1) / TB), TB>>>(cin, W8, xw2, NN);
    k_agg2<<<NB_N, TB>>>(rs, csrc, cw, xw2, b8, dis2, out);
}

// round 7
// speedup vs baseline: 2.3218x; 1.3497x over previous
#include <cuda_runtime.h>
#include <cuda_bf16.h>
#include <cstdint>

#define NN 50000
#define EE 800000
#define FF 128

// ---------------- device scratch ----------------
__device__ float g_deg[NN];
__device__ float g_dis[NN];
__device__ float g_dis2[NN];
__device__ int   g_cnt[NN];
__device__ int   g_cursor[NN];
__device__ int   g_rs[NN + 4];
__device__ int   g_csrc[EE];
__device__ float g_cw[EE];
__device__ float g_bufA[(size_t)NN * FF];
__device__ float g_bufB[(size_t)NN * FF];
__device__ float g_bufC[(size_t)NN * FF];
__device__ float g_xw2[(size_t)NN * 2];
__device__ __nv_bfloat16 g_whi[7 * FF * FF];   // [layer][n][k] K-major
__device__ __nv_bfloat16 g_wlo[7 * FF * FF];

// ---------------- preprocessing ----------------
__global__ void k_init(float* deg, int* cnt, int* cursor) {
    int i = blockIdx.x * blockDim.x + threadIdx.x;
    if (i < NN) { deg[i] = 1.0f; cnt[i] = 0; cursor[i] = 0; }
}

__global__ void k_edge_prep(const int* __restrict__ ei,
                            const float* __restrict__ ew,
                            float* __restrict__ deg, int* __restrict__ cnt) {
    int e = blockIdx.x * blockDim.x + threadIdx.x;
    if (e >= EE) return;
    int d = ei[EE + e];
    atomicAdd(&deg[d], ew[e]);
    atomicAdd(&cnt[d], 1);
}

__global__ void k_dis(const float* __restrict__ deg,
                      float* __restrict__ dis, float* __restrict__ dis2) {
    int i = blockIdx.x * blockDim.x + threadIdx.x;
    if (i < NN) {
        float v = rsqrtf(deg[i]);
        dis[i] = v;
        dis2[i] = v * v;
    }
}

// split weights into bf16 hi/lo, transposed to [n][k]
__global__ void k_wsplit(const float* __restrict__ W1, const float* __restrict__ Wmid,
                         __nv_bfloat16* __restrict__ whi, __nv_bfloat16* __restrict__ wlo) {
    int idx = blockIdx.x * blockDim.x + threadIdx.x;
    if (idx >= 7 * FF * FF) return;
    int l = idx / (FF * FF);
    int r = idx % (FF * FF);
    int k = r >> 7;
    int n = r & 127;
    float w = (l == 0) ? W1[k * FF + n] : Wmid[(size_t)(l - 1) * FF * FF + k * FF + n];
    __nv_bfloat16 hi = __float2bfloat16_rn(w);
    float res = w - __bfloat162float(hi);
    __nv_bfloat16 lo = __float2bfloat16_rn(res);
    whi[(size_t)l * FF * FF + n * FF + k] = hi;
    wlo[(size_t)l * FF * FF + n * FF + k] = lo;
}

// single-block exclusive scan over cnt -> rs (int4)
__global__ void k_scan(const int4* __restrict__ cnt4, int* __restrict__ rs) {
    __shared__ int warp_sums[32];
    __shared__ int carry;
    const int N4 = NN / 4;
    int tid = threadIdx.x;
    int lane = tid & 31, wid = tid >> 5;
    if (tid == 0) carry = 0;
    __syncthreads();
    for (int base = 0; base < N4; base += 1024) {
        int i = base + tid;
        int4 v = make_int4(0, 0, 0, 0);
        if (i < N4) v = cnt4[i];
        int tsum = v.x + v.y + v.z + v.w;
        int x = tsum;
#pragma unroll
        for (int off = 1; off < 32; off <<= 1) {
            int y = __shfl_up_sync(0xFFFFFFFFu, x, off);
            if (lane >= off) x += y;
        }
        if (lane == 31) warp_sums[wid] = x;
        __syncthreads();
        if (wid == 0) {
            int s = warp_sums[lane];
#pragma unroll
            for (int off = 1; off < 32; off <<= 1) {
                int y = __shfl_up_sync(0xFFFFFFFFu, s, off);
                if (lane >= off) s += y;
            }
            warp_sums[lane] = s;
        }
        __syncthreads();
        int warp_off = (wid == 0) ? 0 : warp_sums[wid - 1];
        int excl = carry + warp_off + (x - tsum);
        if (i < N4) {
            int4 o;
            o.x = excl;
            o.y = o.x + v.x;
            o.z = o.y + v.y;
            o.w = o.z + v.z;
            *(int4*)(rs + i * 4) = o;
        }
        __syncthreads();
        if (tid == 0) carry += warp_sums[31];
        __syncthreads();
    }
    if (threadIdx.x == 0) rs[NN] = carry;
}

__global__ void k_fill(const int* __restrict__ ei, const float* __restrict__ ew,
                       const float* __restrict__ dis, const int* __restrict__ rs,
                       int* __restrict__ cursor,
                       int* __restrict__ csrc, float* __restrict__ cw) {
    int e = blockIdx.x * blockDim.x + threadIdx.x;
    if (e >= EE) return;
    int s = ei[e];
    int d = ei[EE + e];
    float nrm = dis[s] * ew[e] * dis[d];
    int p = atomicAdd(&cursor[d], 1);
    int slot = rs[d] + p;
    csrc[slot] = s;
    cw[slot] = nrm;
}

// ---------------- mma.sync bf16 split GEMM ----------------
// xw = (RELU? relu(A) : A) @ W  via  Ahi*Whi + Ahi*Wlo + Alo*Whi (fp32 accum)
// CTA: 128 rows x 128 cols; 8 warps as 2(M) x 4(N); warp tile 64x32.
// K chunked by 32 in padded smem (stride 40 bf16 -> conflict-free).
#define SSTR 40

__device__ __forceinline__ void mma16816(float* d, const uint32_t* a, const uint32_t* b) {
    asm volatile(
        "mma.sync.aligned.m16n8k16.row.col.f32.bf16.bf16.f32 "
        "{%0,%1,%2,%3}, {%4,%5,%6,%7}, {%8,%9}, {%0,%1,%2,%3};"
        : "+f"(d[0]), "+f"(d[1]), "+f"(d[2]), "+f"(d[3])
        : "r"(a[0]), "r"(a[1]), "r"(a[2]), "r"(a[3]), "r"(b[0]), "r"(b[1]));
}

template <bool RELU>
__global__ void __launch_bounds__(256, 2) k_gemm_mma(
    const float* __restrict__ A,
    const __nv_bfloat16* __restrict__ whi, const __nv_bfloat16* __restrict__ wlo,
    float* __restrict__ xw, int M) {
    __shared__ __nv_bfloat16 sAhi[128 * SSTR];
    __shared__ __nv_bfloat16 sAlo[128 * SSTR];
    __shared__ __nv_bfloat16 sWhi[128 * SSTR];
    __shared__ __nv_bfloat16 sWlo[128 * SSTR];

    int tid = threadIdx.x;
    int wid = tid >> 5;
    int lane = tid & 31;
    int g = lane >> 2;       // group id (0-7)
    int tg = lane & 3;       // thread in group
    int warp_m = wid & 1;    // 2 M-tiles of 64
    int warp_n = wid >> 1;   // 4 N-tiles of 32
    int row0 = blockIdx.x * 128;

    float acc[4][4][4];
#pragma unroll
    for (int mf = 0; mf < 4; mf++)
#pragma unroll
        for (int nf = 0; nf < 4; nf++)
#pragma unroll
            for (int r = 0; r < 4; r++) acc[mf][nf][r] = 0.0f;

    for (int k0 = 0; k0 < 128; k0 += 32) {
        // ---- load A chunk [128 rows][32 k] fp32 -> split bf16 hi/lo ----
#pragma unroll
        for (int t = 0; t < 4; t++) {
            int idx = tid + t * 256;     // 1024 float4
            int r = idx >> 3;            // row
            int c4 = idx & 7;            // float4 within 32-k chunk
            int gr = row0 + r;
            float4 v = make_float4(0.f, 0.f, 0.f, 0.f);
            if (gr < M) v = *(const float4*)(A + (size_t)gr * FF + k0 + c4 * 4);
            if (RELU) {
                v.x = fmaxf(v.x, 0.f); v.y = fmaxf(v.y, 0.f);
                v.z = fmaxf(v.z, 0.f); v.w = fmaxf(v.w, 0.f);
            }
            __nv_bfloat16 h0 = __float2bfloat16_rn(v.x);
            __nv_bfloat16 h1 = __float2bfloat16_rn(v.y);
            __nv_bfloat16 h2 = __float2bfloat16_rn(v.z);
            __nv_bfloat16 h3 = __float2bfloat16_rn(v.w);
            __nv_bfloat16 l0 = __float2bfloat16_rn(v.x - __bfloat162float(h0));
            __nv_bfloat16 l1 = __float2bfloat16_rn(v.y - __bfloat162float(h1));
            __nv_bfloat16 l2 = __float2bfloat16_rn(v.z - __bfloat162float(h2));
            __nv_bfloat16 l3 = __float2bfloat16_rn(v.w - __bfloat162float(h3));
            __nv_bfloat162 hh0 = __halves2bfloat162(h0, h1);
            __nv_bfloat162 hh1 = __halves2bfloat162(h2, h3);
            __nv_bfloat162 ll0 = __halves2bfloat162(l0, l1);
            __nv_bfloat162 ll1 = __halves2bfloat162(l2, l3);
            int so = r * SSTR + c4 * 4;
            *(uint2*)&sAhi[so] = make_uint2(*(uint32_t*)&hh0, *(uint32_t*)&hh1);
            *(uint2*)&sAlo[so] = make_uint2(*(uint32_t*)&ll0, *(uint32_t*)&ll1);
        }
        // ---- load W chunk [128 n][32 k] bf16 ----
#pragma unroll
        for (int t = 0; t < 2; t++) {
            int idx = tid + t * 256;     // 512 uint4
            int n = idx >> 2;
            int q = idx & 3;             // 8-bf16 group
            int so = n * SSTR + q * 8;
            *(uint4*)&sWhi[so] = *(const uint4*)(whi + (size_t)n * FF + k0 + q * 8);
            *(uint4*)&sWlo[so] = *(const uint4*)(wlo + (size_t)n * FF + k0 + q * 8);
        }
        __syncthreads();

        // ---- 3 chains x 2 ksteps x 4x4 mma ----
#pragma unroll
        for (int chain = 0; chain < 3; chain++) {
            const __nv_bfloat16* sA = (chain == 2) ? sAlo : sAhi;
            const __nv_bfloat16* sW = (chain == 1) ? sWlo : sWhi;
#pragma unroll
            for (int ks = 0; ks < 2; ks++) {
                int kb = ks * 16;
                uint32_t afr[4][4];
#pragma unroll
                for (int mf = 0; mf < 4; mf++) {
                    int base = (warp_m * 64 + mf * 16 + g) * SSTR + kb + tg * 2;
                    afr[mf][0] = *(const uint32_t*)&sA[base];
                    afr[mf][1] = *(const uint32_t*)&sA[base + 8 * SSTR];
                    afr[mf][2] = *(const uint32_t*)&sA[base + 8];
                    afr[mf][3] = *(const uint32_t*)&sA[base + 8 * SSTR + 8];
                }
                uint32_t bfr[4][2];
#pragma unroll
                for (int nf = 0; nf < 4; nf++) {
                    int base = (warp_n * 32 + nf * 8 + g) * SSTR + kb + tg * 2;
                    bfr[nf][0] = *(const uint32_t*)&sW[base];
                    bfr[nf][1] = *(const uint32_t*)&sW[base + 8];
                }
#pragma unroll
                for (int mf = 0; mf < 4; mf++)
#pragma unroll
                    for (int nf = 0; nf < 4; nf++)
                        mma16816(acc[mf][nf], afr[mf], bfr[nf]);
            }
        }
        __syncthreads();
    }

    // ---- epilogue: write fp32 ----
#pragma unroll
    for (int mf = 0; mf < 4; mf++) {
        int r_up = row0 + warp_m * 64 + mf * 16 + g;
        int r_dn = r_up + 8;
#pragma unroll
        for (int nf = 0; nf < 4; nf++) {
            int col = warp_n * 32 + nf * 8 + tg * 2;
            if (r_up < M)
                *(float2*)(xw + (size_t)r_up * FF + col) =
                    make_float2(acc[mf][nf][0], acc[mf][nf][1]);
            if (r_dn < M)
                *(float2*)(xw + (size_t)r_dn * FF + col) =
                    make_float2(acc[mf][nf][2], acc[mf][nf][3]);
        }
    }
}

// ---------------- CSR aggregation ----------------
__global__ void __launch_bounds__(256) k_agg128(
    const int* __restrict__ rs, const int* __restrict__ csrc,
    const float* __restrict__ cw, const float* __restrict__ xw,
    const float* __restrict__ bias, const float* __restrict__ dis2,
    float* __restrict__ outb) {
    int v = (blockIdx.x * blockDim.x + threadIdx.x) >> 5;
    if (v >= NN) return;
    int lane = threadIdx.x & 31;
    const float4* xwr = (const float4*)xw;

    float4 acc = xwr[(size_t)v * 32 + lane];
    float d2 = dis2[v];
    float4 b = *(const float4*)(bias + lane * 4);
    acc.x = b.x + d2 * acc.x;
    acc.y = b.y + d2 * acc.y;
    acc.z = b.z + d2 * acc.z;
    acc.w = b.w + d2 * acc.w;

    int beg = rs[v], end = rs[v + 1];
    int i = beg;
    for (; i + 3 < end; i += 4) {
        int s0 = csrc[i],     s1 = csrc[i + 1];
        int s2 = csrc[i + 2], s3 = csrc[i + 3];
        float w0 = cw[i],     w1 = cw[i + 1];
        float w2 = cw[i + 2], w3 = cw[i + 3];
        float4 v0 = xwr[(size_t)s0 * 32 + lane];
        float4 v1 = xwr[(size_t)s1 * 32 + lane];
        float4 v2 = xwr[(size_t)s2 * 32 + lane];
        float4 v3 = xwr[(size_t)s3 * 32 + lane];
        acc.x += w0 * v0.x; acc.y += w0 * v0.y; acc.z += w0 * v0.z; acc.w += w0 * v0.w;
        acc.x += w1 * v1.x; acc.y += w1 * v1.y; acc.z += w1 * v1.z; acc.w += w1 * v1.w;
        acc.x += w2 * v2.x; acc.y += w2 * v2.y; acc.z += w2 * v2.z; acc.w += w2 * v2.w;
        acc.x += w3 * v3.x; acc.y += w3 * v3.y; acc.z += w3 * v3.z; acc.w += w3 * v3.w;
    }
    for (; i < end; i++) {
        int s0 = csrc[i];
        float w0 = cw[i];
        float4 v0 = xwr[(size_t)s0 * 32 + lane];
        acc.x += w0 * v0.x; acc.y += w0 * v0.y;
        acc.z += w0 * v0.z; acc.w += w0 * v0.w;
    }
    ((float4*)outb)[(size_t)v * 32 + lane] = acc;
}

// ---------------- layer 8: skinny GEMM (128 -> 2) ----------------
__global__ void __launch_bounds__(256) k_gemm2(
    const float* __restrict__ A, const float* __restrict__ W8,
    float* __restrict__ xw2, int M) {
    __shared__ float Ws[256];
    int tid = threadIdx.x;
    Ws[tid] = W8[tid];
    __syncthreads();

    int w = (blockIdx.x * blockDim.x + tid) >> 5;
    if (w >= M) return;
    int lane = tid & 31;

    float4 v = *(const float4*)(A + (size_t)w * FF + lane * 4);
    v.x = fmaxf(v.x, 0.f); v.y = fmaxf(v.y, 0.f);
    v.z = fmaxf(v.z, 0.f); v.w = fmaxf(v.w, 0.f);
    int k = lane * 4;
    float s0 = v.x * Ws[(k + 0) * 2] + v.y * Ws[(k + 1) * 2] +
               v.z * Ws[(k + 2) * 2] + v.w * Ws[(k + 3) * 2];
    float s1 = v.x * Ws[(k + 0) * 2 + 1] + v.y * Ws[(k + 1) * 2 + 1] +
               v.z * Ws[(k + 2) * 2 + 1] + v.w * Ws[(k + 3) * 2 + 1];
#pragma unroll
    for (int off = 16; off; off >>= 1) {
        s0 += __shfl_xor_sync(0xFFFFFFFFu, s0, off);
        s1 += __shfl_xor_sync(0xFFFFFFFFu, s1, off);
    }
    if (lane == 0) {
        xw2[(size_t)w * 2]     = s0;
        xw2[(size_t)w * 2 + 1] = s1;
    }
}

__global__ void __launch_bounds__(256) k_agg2(
    const int* __restrict__ rs, const int* __restrict__ csrc,
    const float* __restrict__ cw, const float* __restrict__ xw2,
    const float* __restrict__ b8, const float* __restrict__ dis2,
    float* __restrict__ outb) {
    int v = blockIdx.x * blockDim.x + threadIdx.x;
    if (v >= NN) return;
    float2 a = *(const float2*)(xw2 + (size_t)v * 2);
    float d2 = dis2[v];
    float s0 = b8[0] + d2 * a.x;
    float s1 = b8[1] + d2 * a.y;
    int end = rs[v + 1];
    for (int i = rs[v]; i < end; i++) {
        int s = csrc[i];
        float w = cw[i];
        float2 xv = *(const float2*)(xw2 + (size_t)s * 2);
        s0 += w * xv.x;
        s1 += w * xv.y;
    }
    outb[(size_t)v * 2]     = s0;
    outb[(size_t)v * 2 + 1] = s1;
}

// ---------------- launcher ----------------
extern "C" void kernel_launch(void* const* d_in, const int* in_sizes, int n_in,
                              void* d_out, int out_size) {
    const float* x    = (const float*)d_in[0];
    const int*   ei   = (const int*)d_in[1];
    const float* ea   = (const float*)d_in[2];
    const float* W1   = (const float*)d_in[3];
    const float* b1   = (const float*)d_in[4];
    const float* Wmid = (const float*)d_in[5];
    const float* bmid = (const float*)d_in[6];
    const float* W8   = (const float*)d_in[7];
    const float* b8   = (const float*)d_in[8];
    float* out = (float*)d_out;

    float *deg, *dis, *dis2, *bufA, *bufB, *bufC, *xw2, *cw;
    int *cnt, *cursor, *rs, *csrc;
    __nv_bfloat16 *whi, *wlo;
    cudaGetSymbolAddress((void**)&deg,    g_deg);
    cudaGetSymbolAddress((void**)&dis,    g_dis);
    cudaGetSymbolAddress((void**)&dis2,   g_dis2);
    cudaGetSymbolAddress((void**)&cnt,    g_cnt);
    cudaGetSymbolAddress((void**)&cursor, g_cursor);
    cudaGetSymbolAddress((void**)&rs,     g_rs);
    cudaGetSymbolAddress((void**)&csrc,   g_csrc);
    cudaGetSymbolAddress((void**)&cw,     g_cw);
    cudaGetSymbolAddress((void**)&bufA,   g_bufA);
    cudaGetSymbolAddress((void**)&bufB,   g_bufB);
    cudaGetSymbolAddress((void**)&bufC,   g_bufC);
    cudaGetSymbolAddress((void**)&xw2,    g_xw2);
    cudaGetSymbolAddress((void**)&whi,    g_whi);
    cudaGetSymbolAddress((void**)&wlo,    g_wlo);

    const int TB = 256;
    const int NB_N = (NN + TB - 1) / TB;
    const int NB_E = (EE + TB - 1) / TB;

    // precompute: weight split + CSR + norm
    k_wsplit<<<(7 * FF * FF + TB - 1) / TB, TB>>>(W1, Wmid, whi, wlo);
    k_init<<<NB_N, TB>>>(deg, cnt, cursor);
    k_edge_prep<<<NB_E, TB>>>(ei, ea, deg, cnt);
    k_dis<<<NB_N, TB>>>(deg, dis, dis2);
    k_scan<<<1, 1024>>>((const int4*)cnt, rs);
    k_fill<<<NB_E, TB>>>(ei, ea, dis, rs, cursor, csrc, cw);

    const int GEMM_BLOCKS = (NN + 127) / 128;   // 391
    const int AGG_BLOCKS  = (int)(((long long)NN * 32 + TB - 1) / TB);

    // layer 1
    k_gemm_mma<false><<<GEMM_BLOCKS, TB>>>(x, whi, wlo, bufA, NN);
    k_agg128<<<AGG_BLOCKS, TB>>>(rs, csrc, cw, bufA, b1, dis2, bufB);

    // layers 2..7
    const float* cin = bufB;
    float* f1 = bufC;
    for (int i = 0; i < 6; i++) {
        const __nv_bfloat16* wh = whi + (size_t)(i + 1) * FF * FF;
        const __nv_bfloat16* wl = wlo + (size_t)(i + 1) * FF * FF;
        const float* b = bmid + (size_t)i * FF;
        k_gemm_mma<true><<<GEMM_BLOCKS, TB>>>(cin, wh, wl, bufA, NN);
        k_agg128<<<AGG_BLOCKS, TB>>>(rs, csrc, cw, bufA, b, dis2, f1);
        float* oldin = (float*)cin;
        cin = f1;
        f1 = oldin;
    }

    // layer 8
    k_gemm2<<<(int)(((long long)NN * 32 + TB - 1) / TB), TB>>>(cin, W8, xw2, NN);
    k_agg2<<<NB_N, TB>>>(rs, csrc, cw, xw2, b8, dis2, out);
}

// round 8
// speedup vs baseline: 2.3515x; 1.0128x over previous
#include <cuda_runtime.h>
#include <cuda_bf16.h>
#include <cstdint>

#define NN 50000
#define EE 800000
#define FF 128

#define SCAN_BLK 1024
#define SCAN_NB ((NN + SCAN_BLK - 1) / SCAN_BLK)   // 49

// ---------------- device scratch ----------------
__device__ float g_deg[NN];
__device__ float g_dis[NN];
__device__ float g_dis2[NN];
__device__ int   g_cnt[NN];
__device__ int   g_cursor[NN];
__device__ int   g_rs[NN + 4];
__device__ int   g_bsum[SCAN_NB];
__device__ int   g_boff[SCAN_NB];
__device__ int2  g_cs[EE];                 // packed {src, norm-bits}
__device__ float g_bufA[(size_t)NN * FF];
__device__ float g_bufB[(size_t)NN * FF];
__device__ float g_bufC[(size_t)NN * FF];
__device__ float g_xw2[(size_t)NN * 2];
__device__ __nv_bfloat16 g_whi[7 * FF * FF];   // [layer][n][k] K-major
__device__ __nv_bfloat16 g_wlo[7 * FF * FF];

// ---------------- preprocessing ----------------
__global__ void k_init(float* deg, int* cnt, int* cursor) {
    int i = blockIdx.x * blockDim.x + threadIdx.x;
    if (i < NN) { deg[i] = 1.0f; cnt[i] = 0; cursor[i] = 0; }
}

__global__ void k_edge_prep(const int* __restrict__ ei,
                            const float* __restrict__ ew,
                            float* __restrict__ deg, int* __restrict__ cnt) {
    int e = blockIdx.x * blockDim.x + threadIdx.x;
    if (e >= EE) return;
    int d = ei[EE + e];
    atomicAdd(&deg[d], ew[e]);
    atomicAdd(&cnt[d], 1);
}

__global__ void k_dis(const float* __restrict__ deg,
                      float* __restrict__ dis, float* __restrict__ dis2) {
    int i = blockIdx.x * blockDim.x + threadIdx.x;
    if (i < NN) {
        float v = rsqrtf(deg[i]);
        dis[i] = v;
        dis2[i] = v * v;
    }
}

// split weights into bf16 hi/lo, transposed to [n][k]
__global__ void k_wsplit(const float* __restrict__ W1, const float* __restrict__ Wmid,
                         __nv_bfloat16* __restrict__ whi, __nv_bfloat16* __restrict__ wlo) {
    int idx = blockIdx.x * blockDim.x + threadIdx.x;
    if (idx >= 7 * FF * FF) return;
    int l = idx / (FF * FF);
    int r = idx % (FF * FF);
    int k = r >> 7;
    int n = r & 127;
    float w = (l == 0) ? W1[k * FF + n] : Wmid[(size_t)(l - 1) * FF * FF + k * FF + n];
    __nv_bfloat16 hi = __float2bfloat16_rn(w);
    float res = w - __bfloat162float(hi);
    __nv_bfloat16 lo = __float2bfloat16_rn(res);
    whi[(size_t)l * FF * FF + n * FF + k] = hi;
    wlo[(size_t)l * FF * FF + n * FF + k] = lo;
}

// ---------------- 3-phase scan ----------------
// phase 1: per-block exclusive scan (1024 elems/block) + block sum
__global__ void __launch_bounds__(SCAN_BLK) k_scan1(
    const int* __restrict__ cnt, int* __restrict__ rs, int* __restrict__ bsum) {
    __shared__ int warp_sums[32];
    int tid = threadIdx.x;
    int lane = tid & 31, wid = tid >> 5;
    int i = blockIdx.x * SCAN_BLK + tid;
    int v = (i < NN) ? cnt[i] : 0;
    int x = v;
#pragma unroll
    for (int off = 1; off < 32; off <<= 1) {
        int y = __shfl_up_sync(0xFFFFFFFFu, x, off);
        if (lane >= off) x += y;
    }
    if (lane == 31) warp_sums[wid] = x;
    __syncthreads();
    if (wid == 0) {
        int s = warp_sums[lane];
#pragma unroll
        for (int off = 1; off < 32; off <<= 1) {
            int y = __shfl_up_sync(0xFFFFFFFFu, s, off);
            if (lane >= off) s += y;
        }
        warp_sums[lane] = s;
    }
    __syncthreads();
    int warp_off = (wid == 0) ? 0 : warp_sums[wid - 1];
    if (i < NN) rs[i] = warp_off + (x - v);
    if (tid == SCAN_BLK - 1) bsum[blockIdx.x] = warp_off + x;
}

// phase 2: single small block scans block sums (SCAN_NB <= 64)
__global__ void k_scan2(const int* __restrict__ bsum, int* __restrict__ boff,
                        int* __restrict__ rs) {
    __shared__ int sh[64];
    int tid = threadIdx.x;
    sh[tid] = (tid < SCAN_NB) ? bsum[tid] : 0;
    __syncthreads();
    if (tid == 0) {
        int run = 0;
        for (int b = 0; b < SCAN_NB; b++) {
            boff[b] = run;
            run += sh[b];
        }
        rs[NN] = run;
    }
}

// phase 3: add block offsets
__global__ void __launch_bounds__(SCAN_BLK) k_scan3(
    int* __restrict__ rs, const int* __restrict__ boff) {
    int i = blockIdx.x * SCAN_BLK + threadIdx.x;
    if (i < NN) rs[i] += boff[blockIdx.x];
}

__global__ void k_fill(const int* __restrict__ ei, const float* __restrict__ ew,
                       const float* __restrict__ dis, const int* __restrict__ rs,
                       int* __restrict__ cursor, int2* __restrict__ cs) {
    int e = blockIdx.x * blockDim.x + threadIdx.x;
    if (e >= EE) return;
    int s = ei[e];
    int d = ei[EE + e];
    float nrm = dis[s] * ew[e] * dis[d];
    int p = atomicAdd(&cursor[d], 1);
    cs[rs[d] + p] = make_int2(s, __float_as_int(nrm));
}

// ---------------- mma.sync bf16 split GEMM ----------------
#define SSTR 40

__device__ __forceinline__ void mma16816(float* d, const uint32_t* a, const uint32_t* b) {
    asm volatile(
        "mma.sync.aligned.m16n8k16.row.col.f32.bf16.bf16.f32 "
        "{%0,%1,%2,%3}, {%4,%5,%6,%7}, {%8,%9}, {%0,%1,%2,%3};"
        : "+f"(d[0]), "+f"(d[1]), "+f"(d[2]), "+f"(d[3])
        : "r"(a[0]), "r"(a[1]), "r"(a[2]), "r"(a[3]), "r"(b[0]), "r"(b[1]));
}

template <bool RELU>
__global__ void __launch_bounds__(256, 2) k_gemm_mma(
    const float* __restrict__ A,
    const __nv_bfloat16* __restrict__ whi, const __nv_bfloat16* __restrict__ wlo,
    float* __restrict__ xw, int M) {
    __shared__ __nv_bfloat16 sAhi[128 * SSTR];
    __shared__ __nv_bfloat16 sAlo[128 * SSTR];
    __shared__ __nv_bfloat16 sWhi[128 * SSTR];
    __shared__ __nv_bfloat16 sWlo[128 * SSTR];

    int tid = threadIdx.x;
    int wid = tid >> 5;
    int lane = tid & 31;
    int g = lane >> 2;
    int tg = lane & 3;
    int warp_m = wid & 1;
    int warp_n = wid >> 1;
    int row0 = blockIdx.x * 128;

    float acc[4][4][4];
#pragma unroll
    for (int mf = 0; mf < 4; mf++)
#pragma unroll
        for (int nf = 0; nf < 4; nf++)
#pragma unroll
            for (int r = 0; r < 4; r++) acc[mf][nf][r] = 0.0f;

    for (int k0 = 0; k0 < 128; k0 += 32) {
#pragma unroll
        for (int t = 0; t < 4; t++) {
            int idx = tid + t * 256;
            int r = idx >> 3;
            int c4 = idx & 7;
            int gr = row0 + r;
            float4 v = make_float4(0.f, 0.f, 0.f, 0.f);
            if (gr < M) v = *(const float4*)(A + (size_t)gr * FF + k0 + c4 * 4);
            if (RELU) {
                v.x = fmaxf(v.x, 0.f); v.y = fmaxf(v.y, 0.f);
                v.z = fmaxf(v.z, 0.f); v.w = fmaxf(v.w, 0.f);
            }
            __nv_bfloat16 h0 = __float2bfloat16_rn(v.x);
            __nv_bfloat16 h1 = __float2bfloat16_rn(v.y);
            __nv_bfloat16 h2 = __float2bfloat16_rn(v.z);
            __nv_bfloat16 h3 = __float2bfloat16_rn(v.w);
            __nv_bfloat16 l0 = __float2bfloat16_rn(v.x - __bfloat162float(h0));
            __nv_bfloat16 l1 = __float2bfloat16_rn(v.y - __bfloat162float(h1));
            __nv_bfloat16 l2 = __float2bfloat16_rn(v.z - __bfloat162float(h2));
            __nv_bfloat16 l3 = __float2bfloat16_rn(v.w - __bfloat162float(h3));
            __nv_bfloat162 hh0 = __halves2bfloat162(h0, h1);
            __nv_bfloat162 hh1 = __halves2bfloat162(h2, h3);
            __nv_bfloat162 ll0 = __halves2bfloat162(l0, l1);
            __nv_bfloat162 ll1 = __halves2bfloat162(l2, l3);
            int so = r * SSTR + c4 * 4;
            *(uint2*)&sAhi[so] = make_uint2(*(uint32_t*)&hh0, *(uint32_t*)&hh1);
            *(uint2*)&sAlo[so] = make_uint2(*(uint32_t*)&ll0, *(uint32_t*)&ll1);
        }
#pragma unroll
        for (int t = 0; t < 2; t++) {
            int idx = tid + t * 256;
            int n = idx >> 2;
            int q = idx & 3;
            int so = n * SSTR + q * 8;
            *(uint4*)&sWhi[so] = *(const uint4*)(whi + (size_t)n * FF + k0 + q * 8);
            *(uint4*)&sWlo[so] = *(const uint4*)(wlo + (size_t)n * FF + k0 + q * 8);
        }
        __syncthreads();

#pragma unroll
        for (int chain = 0; chain < 3; chain++) {
            const __nv_bfloat16* sA = (chain == 2) ? sAlo : sAhi;
            const __nv_bfloat16* sW = (chain == 1) ? sWlo : sWhi;
#pragma unroll
            for (int ks = 0; ks < 2; ks++) {
                int kb = ks * 16;
                uint32_t afr[4][4];
#pragma unroll
                for (int mf = 0; mf < 4; mf++) {
                    int base = (warp_m * 64 + mf * 16 + g) * SSTR + kb + tg * 2;
                    afr[mf][0] = *(const uint32_t*)&sA[base];
                    afr[mf][1] = *(const uint32_t*)&sA[base + 8 * SSTR];
                    afr[mf][2] = *(const uint32_t*)&sA[base + 8];
                    afr[mf][3] = *(const uint32_t*)&sA[base + 8 * SSTR + 8];
                }
                uint32_t bfr[4][2];
#pragma unroll
                for (int nf = 0; nf < 4; nf++) {
                    int base = (warp_n * 32 + nf * 8 + g) * SSTR + kb + tg * 2;
                    bfr[nf][0] = *(const uint32_t*)&sW[base];
                    bfr[nf][1] = *(const uint32_t*)&sW[base + 8];
                }
#pragma unroll
                for (int mf = 0; mf < 4; mf++)
#pragma unroll
                    for (int nf = 0; nf < 4; nf++)
                        mma16816(acc[mf][nf], afr[mf], bfr[nf]);
            }
        }
        __syncthreads();
    }

#pragma unroll
    for (int mf = 0; mf < 4; mf++) {
        int r_up = row0 + warp_m * 64 + mf * 16 + g;
        int r_dn = r_up + 8;
#pragma unroll
        for (int nf = 0; nf < 4; nf++) {
            int col = warp_n * 32 + nf * 8 + tg * 2;
            if (r_up < M)
                *(float2*)(xw + (size_t)r_up * FF + col) =
                    make_float2(acc[mf][nf][0], acc[mf][nf][1]);
            if (r_dn < M)
                *(float2*)(xw + (size_t)r_dn * FF + col) =
                    make_float2(acc[mf][nf][2], acc[mf][nf][3]);
        }
    }
}

// ---------------- CSR aggregation ----------------
__device__ __forceinline__ float4 ldcg4(const float* p) {
    float4 v;
    asm("ld.global.cg.v4.f32 {%0,%1,%2,%3}, [%4];"
        : "=f"(v.x), "=f"(v.y), "=f"(v.z), "=f"(v.w) : "l"(p));
    return v;
}

__global__ void __launch_bounds__(256) k_agg128(
    const int* __restrict__ rs, const int2* __restrict__ cs,
    const float* __restrict__ xw,
    const float* __restrict__ bias, const float* __restrict__ dis2,
    float* __restrict__ outb) {
    int v = (blockIdx.x * blockDim.x + threadIdx.x) >> 5;
    if (v >= NN) return;
    int lane = threadIdx.x & 31;

    float4 acc = ldcg4(xw + (size_t)v * FF + lane * 4);
    float d2 = dis2[v];
    float4 b = *(const float4*)(bias + lane * 4);
    acc.x = b.x + d2 * acc.x;
    acc.y = b.y + d2 * acc.y;
    acc.z = b.z + d2 * acc.z;
    acc.w = b.w + d2 * acc.w;

    int beg = rs[v], end = rs[v + 1];
    int i = beg;
    for (; i + 3 < end; i += 4) {
        int2 e0 = cs[i],     e1 = cs[i + 1];
        int2 e2 = cs[i + 2], e3 = cs[i + 3];
        float4 v0 = ldcg4(xw + (size_t)e0.x * FF + lane * 4);
        float4 v1 = ldcg4(xw + (size_t)e1.x * FF + lane * 4);
        float4 v2 = ldcg4(xw + (size_t)e2.x * FF + lane * 4);
        float4 v3 = ldcg4(xw + (size_t)e3.x * FF + lane * 4);
        float w0 = __int_as_float(e0.y), w1 = __int_as_float(e1.y);
        float w2 = __int_as_float(e2.y), w3 = __int_as_float(e3.y);
        acc.x += w0 * v0.x; acc.y += w0 * v0.y; acc.z += w0 * v0.z; acc.w += w0 * v0.w;
        acc.x += w1 * v1.x; acc.y += w1 * v1.y; acc.z += w1 * v1.z; acc.w += w1 * v1.w;
        acc.x += w2 * v2.x; acc.y += w2 * v2.y; acc.z += w2 * v2.z; acc.w += w2 * v2.w;
        acc.x += w3 * v3.x; acc.y += w3 * v3.y; acc.z += w3 * v3.z; acc.w += w3 * v3.w;
    }
    for (; i < end; i++) {
        int2 e0 = cs[i];
        float w0 = __int_as_float(e0.y);
        float4 v0 = ldcg4(xw + (size_t)e0.x * FF + lane * 4);
        acc.x += w0 * v0.x; acc.y += w0 * v0.y;
        acc.z += w0 * v0.z; acc.w += w0 * v0.w;
    }
    ((float4*)outb)[(size_t)v * 32 + lane] = acc;
}

// ---------------- layer 8: skinny GEMM (128 -> 2) ----------------
__global__ void __launch_bounds__(256) k_gemm2(
    const float* __restrict__ A, const float* __restrict__ W8,
    float* __restrict__ xw2, int M) {
    __shared__ float Ws[256];
    int tid = threadIdx.x;
    Ws[tid] = W8[tid];
    __syncthreads();

    int w = (blockIdx.x * blockDim.x + tid) >> 5;
    if (w >= M) return;
    int lane = tid & 31;

    float4 v = *(const float4*)(A + (size_t)w * FF + lane * 4);
    v.x = fmaxf(v.x, 0.f); v.y = fmaxf(v.y, 0.f);
    v.z = fmaxf(v.z, 0.f); v.w = fmaxf(v.w, 0.f);
    int k = lane * 4;
    float s0 = v.x * Ws[(k + 0) * 2] + v.y * Ws[(k + 1) * 2] +
               v.z * Ws[(k + 2) * 2] + v.w * Ws[(k + 3) * 2];
    float s1 = v.x * Ws[(k + 0) * 2 + 1] + v.y * Ws[(k + 1) * 2 + 1] +
               v.z * Ws[(k + 2) * 2 + 1] + v.w * Ws[(k + 3) * 2 + 1];
#pragma unroll
    for (int off = 16; off; off >>= 1) {
        s0 += __shfl_xor_sync(0xFFFFFFFFu, s0, off);
        s1 += __shfl_xor_sync(0xFFFFFFFFu, s1, off);
    }
    if (lane == 0) {
        xw2[(size_t)w * 2]     = s0;
        xw2[(size_t)w * 2 + 1] = s1;
    }
}

__global__ void __launch_bounds__(256) k_agg2(
    const int* __restrict__ rs, const int2* __restrict__ cs,
    const float* __restrict__ xw2,
    const float* __restrict__ b8, const float* __restrict__ dis2,
    float* __restrict__ outb) {
    int v = blockIdx.x * blockDim.x + threadIdx.x;
    if (v >= NN) return;
    float2 a = *(const float2*)(xw2 + (size_t)v * 2);
    float d2 = dis2[v];
    float s0 = b8[0] + d2 * a.x;
    float s1 = b8[1] + d2 * a.y;
    int end = rs[v + 1];
    for (int i = rs[v]; i < end; i++) {
        int2 e = cs[i];
        float w = __int_as_float(e.y);
        float2 xv = *(const float2*)(xw2 + (size_t)e.x * 2);
        s0 += w * xv.x;
        s1 += w * xv.y;
    }
    outb[(size_t)v * 2]     = s0;
    outb[(size_t)v * 2 + 1] = s1;
}

// ---------------- launcher ----------------
extern "C" void kernel_launch(void* const* d_in, const int* in_sizes, int n_in,
                              void* d_out, int out_size) {
    const float* x    = (const float*)d_in[0];
    const int*   ei   = (const int*)d_in[1];
    const float* ea   = (const float*)d_in[2];
    const float* W1   = (const float*)d_in[3];
    const float* b1   = (const float*)d_in[4];
    const float* Wmid = (const float*)d_in[5];
    const float* bmid = (const float*)d_in[6];
    const float* W8   = (const float*)d_in[7];
    const float* b8   = (const float*)d_in[8];
    float* out = (float*)d_out;

    float *deg, *dis, *dis2, *bufA, *bufB, *bufC, *xw2;
    int *cnt, *cursor, *rs, *bsum, *boff;
    int2* cs;
    __nv_bfloat16 *whi, *wlo;
    cudaGetSymbolAddress((void**)&deg,    g_deg);
    cudaGetSymbolAddress((void**)&dis,    g_dis);
    cudaGetSymbolAddress((void**)&dis2,   g_dis2);
    cudaGetSymbolAddress((void**)&cnt,    g_cnt);
    cudaGetSymbolAddress((void**)&cursor, g_cursor);
    cudaGetSymbolAddress((void**)&rs,     g_rs);
    cudaGetSymbolAddress((void**)&bsum,   g_bsum);
    cudaGetSymbolAddress((void**)&boff,   g_boff);
    cudaGetSymbolAddress((void**)&cs,     g_cs);
    cudaGetSymbolAddress((void**)&bufA,   g_bufA);
    cudaGetSymbolAddress((void**)&bufB,   g_bufB);
    cudaGetSymbolAddress((void**)&bufC,   g_bufC);
    cudaGetSymbolAddress((void**)&xw2,    g_xw2);
    cudaGetSymbolAddress((void**)&whi,    g_whi);
    cudaGetSymbolAddress((void**)&wlo,    g_wlo);

    const int TB = 256;
    const int NB_N = (NN + TB - 1) / TB;
    const int NB_E = (EE + TB - 1) / TB;

    // precompute: weight split + CSR + norm
    k_wsplit<<<(7 * FF * FF + TB - 1) / TB, TB>>>(W1, Wmid, whi, wlo);
    k_init<<<NB_N, TB>>>(deg, cnt, cursor);
    k_edge_prep<<<NB_E, TB>>>(ei, ea, deg, cnt);
    k_dis<<<NB_N, TB>>>(deg, dis, dis2);
    k_scan1<<<SCAN_NB, SCAN_BLK>>>(cnt, rs, bsum);
    k_scan2<<<1, 64>>>(bsum, boff, rs);
    k_scan3<<<SCAN_NB, SCAN_BLK>>>(rs, boff);
    k_fill<<<NB_E, TB>>>(ei, ea, dis, rs, cursor, cs);

    const int GEMM_BLOCKS = (NN + 127) / 128;
    const int AGG_BLOCKS  = (int)(((long long)NN * 32 + TB - 1) / TB);

    // layer 1
    k_gemm_mma<false><<<GEMM_BLOCKS, TB>>>(x, whi, wlo, bufA, NN);
    k_agg128<<<AGG_BLOCKS, TB>>>(rs, cs, bufA, b1, dis2, bufB);

    // layers 2..7
    const float* cin = bufB;
    float* f1 = bufC;
    for (int i = 0; i < 6; i++) {
        const __nv_bfloat16* wh = whi + (size_t)(i + 1) * FF * FF;
        const __nv_bfloat16* wl = wlo + (size_t)(i + 1) * FF * FF;
        const float* b = bmid + (size_t)i * FF;
        k_gemm_mma<true><<<GEMM_BLOCKS, TB>>>(cin, wh, wl, bufA, NN);
        k_agg128<<<AGG_BLOCKS, TB>>>(rs, cs, bufA, b, dis2, f1);
        float* oldin = (float*)cin;
        cin = f1;
        f1 = oldin;
    }

    // layer 8
    k_gemm2<<<(int)(((long long)NN * 32 + TB - 1) / TB), TB>>>(cin, W8, xw2, NN);
    k_agg2<<<NB_N, TB>>>(rs, cs, xw2, b8, dis2, out);
}